// round 14
// baseline (speedup 1.0000x reference)
#include <cuda_runtime.h>
#include <cuda_fp16.h>
#include <math.h>
#include <stdint.h>

// ---------------------------------------------------------------------------
// Problem constants
// ---------------------------------------------------------------------------
#define TOKS 19600
#define PIX  16384
#define NBH  1200
#define NTOK 196

// ---------------------------------------------------------------------------
// Scratch (static __device__ arrays; no allocation anywhere)
// ---------------------------------------------------------------------------
__device__ float g_x1  [16384u * 768u];             // residual-1 (fp32)

__device__ __align__(256) __half g_qkv_h[3u * 1200u * 196u * 64u]; // [w][bh][n][d]
__device__ __align__(256) __half g_win_h[19600u * 768u];   // LN1+partition
__device__ __align__(256) __half g_att_h[19600u * 768u];
__device__ __align__(256) __half g_ln2_h[16384u * 768u];
__device__ __align__(256) __half g_mlp_h[16384u * 3072u];
// transposed (N-major, K contiguous) fp16 weights
__device__ __align__(256) __half g_qkvwt_h[2304u * 768u];
__device__ __align__(256) __half g_projwt_h[768u * 768u];
__device__ __align__(256) __half g_w1t_h[3072u * 768u];
__device__ __align__(256) __half g_w2t_h[768u * 3072u];

// ---------------------------------------------------------------------------
// PTX helpers — sm_80-era features only (harness PTX pass targets plain
// sm_103 which rejects tcgen05/TMEM; mma.sync/ldmatrix/cp.async are fine).
// ---------------------------------------------------------------------------
__device__ __forceinline__ uint32_t smem_u32(const void* p) {
    uint32_t a;
    asm("{ .reg .u64 t; cvta.to.shared.u64 t, %1; cvt.u32.u64 %0, t; }"
        : "=r"(a) : "l"(p));
    return a;
}
__device__ __forceinline__ void cp_async16(uint32_t s, const void* g, uint32_t sz) {
    asm volatile("cp.async.cg.shared.global [%0], [%1], 16, %2;"
                 :: "r"(s), "l"(g), "r"(sz) : "memory");
}
__device__ __forceinline__ void cp_commit() {
    asm volatile("cp.async.commit_group;" ::: "memory");
}
template <int N> __device__ __forceinline__ void cp_wait() {
    asm volatile("cp.async.wait_group %0;" :: "n"(N) : "memory");
}
__device__ __forceinline__ void ldsm4(uint32_t* r, uint32_t addr) {
    asm volatile("ldmatrix.sync.aligned.m8n8.x4.shared.b16 {%0,%1,%2,%3}, [%4];"
                 : "=r"(r[0]), "=r"(r[1]), "=r"(r[2]), "=r"(r[3]) : "r"(addr));
}
__device__ __forceinline__ void mma16816_h(float* c, const uint32_t* a,
                                           const uint32_t* b) {
    asm volatile(
        "mma.sync.aligned.m16n8k16.row.col.f32.f16.f16.f32 "
        "{%0,%1,%2,%3}, {%4,%5,%6,%7}, {%8,%9}, {%0,%1,%2,%3};"
        : "+f"(c[0]), "+f"(c[1]), "+f"(c[2]), "+f"(c[3])
        : "r"(a[0]), "r"(a[1]), "r"(a[2]), "r"(a[3]), "r"(b[0]), "r"(b[1]));
}
__device__ __forceinline__ float gelu_exact(float x) {
    return 0.5f * x * (1.0f + erff(x * 0.70710678118654752440f));
}
// FMA-pipe exp (avoids the 0.5/cyc/SM MUFU bottleneck). Valid for x <= 0,
// rel err ~4e-5.
__device__ __forceinline__ float fexp(float x) {
    x = fmaxf(x, -80.0f);
    float y = x * 1.44269504f;
    float t = __fadd_rn(y, 12582912.0f);
    int ni = __float_as_int(t) - 0x4B400000;
    float f = __fsub_rn(y, __fsub_rn(t, 12582912.0f));
    float p = 0.009618130f;
    p = fmaf(p, f, 0.055504110f);
    p = fmaf(p, f, 0.240226507f);
    p = fmaf(p, f, 0.693147181f);
    p = fmaf(p, f, 1.0f);
    return __int_as_float(__float_as_int(p) + (ni << 23));
}

// ---------------------------------------------------------------------------
// LN (+ optional window-partition gather) -> fp16
// ---------------------------------------------------------------------------
__global__ void ln_h_kernel(const float* __restrict__ in,
                            const float* __restrict__ gamma,
                            const float* __restrict__ beta,
                            __half* __restrict__ oh, int partition) {
    __shared__ float red_s[8], red_q[8];
    int r = blockIdx.x, t = threadIdx.x;
    size_t dst = (size_t)r * 768;
    const float* src;
    if (partition) {
        int wid = r / 196, n = r % 196;
        int b = wid / 25, wi = (wid % 25) / 5, wj = wid % 5;
        int hh = wi * 14 + n / 14, ww = wj * 14 + n % 14;
        if (hh >= 64 || ww >= 64) {
            __half z = __float2half(0.0f);
            for (int c = t; c < 768; c += 256) oh[dst + c] = z;
            return;
        }
        src = in + ((size_t)((b * 64 + hh) * 64 + ww)) * 768;
    } else {
        src = in + (size_t)r * 768;
    }
    float v0 = src[t], v1 = src[t + 256], v2 = src[t + 512];
    float s = v0 + v1 + v2, q = v0 * v0 + v1 * v1 + v2 * v2;
    #pragma unroll
    for (int off = 16; off > 0; off >>= 1) {
        s += __shfl_xor_sync(0xffffffffu, s, off);
        q += __shfl_xor_sync(0xffffffffu, q, off);
    }
    int warp = t >> 5, lane = t & 31;
    if (lane == 0) { red_s[warp] = s; red_q[warp] = q; }
    __syncthreads();
    float st = 0.f, qt = 0.f;
    #pragma unroll
    for (int i = 0; i < 8; i++) { st += red_s[i]; qt += red_q[i]; }
    float mean = st * (1.0f / 768.0f);
    float var  = qt * (1.0f / 768.0f) - mean * mean;
    float rstd = rsqrtf(var + 1e-5f);
    #pragma unroll
    for (int k = 0; k < 3; k++) {
        int c = t + k * 256;
        float vv = (k == 0 ? v0 : (k == 1 ? v1 : v2));
        oh[dst + c] = __float2half((vv - mean) * rstd * gamma[c] + beta[c]);
    }
}

// ---------------------------------------------------------------------------
// Weight transpose: W[K,N] fp32 -> T[N,K] fp16
// ---------------------------------------------------------------------------
__global__ void tsplit_h_kernel(const float* __restrict__ W,
                                __half* __restrict__ T, int Kd, int Nd) {
    __shared__ float tile[32][33];
    int n0 = blockIdx.x * 32, k0 = blockIdx.y * 32;
    int tx = threadIdx.x & 31, ty = threadIdx.x >> 5;
    #pragma unroll
    for (int i = 0; i < 4; i++)
        tile[ty + i * 8][tx] = W[(size_t)(k0 + ty + i * 8) * Nd + n0 + tx];
    __syncthreads();
    #pragma unroll
    for (int i = 0; i < 4; i++) {
        int n = n0 + ty + i * 8, k = k0 + tx;
        T[(size_t)n * Kd + k] = __float2half(tile[tx][ty + i * 8]);
    }
}

// ---------------------------------------------------------------------------
// Tensor-core attention, 13 warps, one strip per warp, fused rel-pos bias
// with k-major broadcast mapping (unchanged from R13 — the 1475us build).
// ---------------------------------------------------------------------------
#define ATHREADS 416
#define OFF_Q 0
#define OFF_K 29952
#define OFF_V 62208
#define OFF_S 91904
#define OFF_RT (OFF_S + 13 * 7424)          // 188416: rel tables 2 x 27x64 f32
#define OFF_RH (OFF_RT + 13824)             // 202240: relh 196x14 f32
#define OFF_RW (OFF_RH + 10976)             // 213216: relw 196x14 f32
#define ATC_SMEM (OFF_RW + 10976)           // 224192 B

__global__ __launch_bounds__(ATHREADS)
void attn_tc_kernel(const __half* __restrict__ qkv,
                    const float* __restrict__ rph,
                    const float* __restrict__ rpw,
                    __half* __restrict__ outh) {
    extern __shared__ char asmem[];
    uint32_t smemb = smem_u32(asmem);
    __half* Qs = (__half*)(asmem + OFF_Q);   // stride 72
    __half* Ks = (__half*)(asmem + OFF_K);   // stride 72
    __half* Vt = (__half*)(asmem + OFF_V);   // stride 232, [ch][tok]
    float* RTh = (float*)(asmem + OFF_RT);          // 27x64
    float* RTw = (float*)(asmem + OFF_RT + 6912);   // 27x64
    float* RelHs = (float*)(asmem + OFF_RH);        // [196][14]
    float* RelWs = (float*)(asmem + OFF_RW);        // [196][14]

    int bh = blockIdx.x;
    int tid = threadIdx.x, warp = tid >> 5, lane = tid & 31;
    const __half* qp = qkv + ((size_t)0 * NBH + bh) * NTOK * 64;
    const __half* kp = qkv + ((size_t)1 * NBH + bh) * NTOK * 64;
    const __half* vp = qkv + ((size_t)2 * NBH + bh) * NTOK * 64;

    const uint4 z4 = make_uint4(0, 0, 0, 0);
    for (int idx = tid; idx < 208 * 8; idx += ATHREADS) {
        int row = idx >> 3, c8 = (idx & 7) * 8;
        uint4 v = (row < 196) ? *(const uint4*)(qp + row * 64 + c8) : z4;
        *(uint4*)(Qs + row * 72 + c8) = v;
    }
    for (int idx = tid; idx < 224 * 8; idx += ATHREADS) {
        int row = idx >> 3, c8 = (idx & 7) * 8;
        uint4 v = (row < 196) ? *(const uint4*)(kp + row * 64 + c8) : z4;
        *(uint4*)(Ks + row * 72 + c8) = v;
    }
    for (int idx = tid; idx < 224 * 64; idx += ATHREADS) {
        int tok = idx >> 6, ch = idx & 63;
        Vt[ch * 232 + tok] = (tok < 196) ? vp[tok * 64 + ch] : __float2half(0.f);
    }
    for (int idx = tid; idx < 27 * 64; idx += ATHREADS) {
        RTh[idx] = rph[idx];
        RTw[idx] = rpw[idx];
    }
    __syncthreads();

    // ---- fused rel-pos bias, k-major mapping (table-row broadcast) ----
    for (int p = tid; p < 14 * 196; p += ATHREADS) {
        int ki = p / 196, row = p % 196;
        const __half* qr = Qs + row * 72;
        const float* rp = RTh + (row / 14 - ki + 13) * 64;
        float s = 0.f;
        #pragma unroll 8
        for (int c = 0; c < 64; c++) s += __half2float(qr[c]) * rp[c];
        RelHs[row * 14 + ki] = s;
    }
    for (int p = tid; p < 14 * 196; p += ATHREADS) {
        int kj = p / 196, rem = p % 196;
        int qj = rem / 14, qi = rem % 14;
        int row = qi * 14 + qj;
        const __half* qr = Qs + row * 72;
        const float* rp = RTw + (qj - kj + 13) * 64;
        float s = 0.f;
        #pragma unroll 8
        for (int c = 0; c < 64; c++) s += __half2float(qr[c]) * rp[c];
        RelWs[row * 14 + kj] = s;
    }
    __syncthreads();

    int win = bh / 12, h = bh % 12;
    size_t obase = (size_t)win * NTOK * 768 + h * 64;

    int a_row = (lane & 7) + ((lane >> 3) & 1) * 8;
    int a_k   = (lane >> 4) * 8;
    int b_row = (lane & 7) + (lane >> 4) * 8;
    int b_k   = ((lane >> 3) & 1) * 8;

    __half* Sp = (__half*)(asmem + OFF_S + warp * 7424);       // [16][232]
    uint32_t sbase_w = smemb + OFF_S + (uint32_t)warp * 7424;

    {
        int strip = warp;               // 0..12, one strip per warp
        int row0 = strip * 16;

        // ---------- S = Q @ K^T ----------
        uint32_t Af[16];
        {
            uint32_t qb = smemb + OFF_Q + (uint32_t)((row0 + a_row) * 72) * 2;
            #pragma unroll
            for (int kt = 0; kt < 4; kt++)
                ldsm4(&Af[kt * 4], qb + (uint32_t)(kt * 16 + a_k) * 2);
        }
        #pragma unroll 2
        for (int n2 = 0; n2 < 14; n2++) {
            uint32_t Bf[16];
            uint32_t kb = smemb + OFF_K + (uint32_t)((n2 * 16 + b_row) * 72) * 2;
            #pragma unroll
            for (int kt = 0; kt < 4; kt++)
                ldsm4(&Bf[kt * 4], kb + (uint32_t)(kt * 16 + b_k) * 2);
            float ac0[4] = {0.f, 0.f, 0.f, 0.f};
            float ac1[4] = {0.f, 0.f, 0.f, 0.f};
            #pragma unroll
            for (int kt = 0; kt < 4; kt++) {
                mma16816_h(ac0, &Af[kt * 4], &Bf[kt * 4]);
                mma16816_h(ac1, &Af[kt * 4], &Bf[kt * 4 + 2]);
            }
            int r = lane >> 2, cc = (lane & 3) * 2;
            int col = n2 * 16 + cc;
            *(__half2*)(Sp + r * 232 + col)           = __floats2half2_rn(ac0[0], ac0[1]);
            *(__half2*)(Sp + (r + 8) * 232 + col)     = __floats2half2_rn(ac0[2], ac0[3]);
            *(__half2*)(Sp + r * 232 + col + 8)       = __floats2half2_rn(ac1[0], ac1[1]);
            *(__half2*)(Sp + (r + 8) * 232 + col + 8) = __floats2half2_rn(ac1[2], ac1[3]);
        }
        __syncwarp();

        // ---------- softmax: 2 lanes/row, register-hoisted bias ----------
        float inv;
        {
            int srow = lane >> 1, half_ = lane & 1;
            int qrow = row0 + srow;
            int rr = qrow < 196 ? qrow : 195;
            const float* RH = RelHs + rr * 14;
            const float* RW = RelWs + rr * 14;
            float rwv[14];
            #pragma unroll
            for (int j = 0; j < 14; j++) rwv[j] = RW[j];
            __half* Srow = Sp + srow * 232 + half_ * 112;
            int ki0 = half_ * 8;
            int nki = half_ ? 6 : 8;        // valid cols: 112 or 84
            float m = -1e30f;
            int c = 0;
            for (int ib = 0; ib < nki; ib++) {
                float rh = RH[ki0 + ib];
                #pragma unroll
                for (int j = 0; j < 14; j++) {
                    float v = __half2float(Srow[c]) * 0.125f + rh + rwv[j];
                    Srow[c] = __float2half(v);
                    m = fmaxf(m, v);
                    c++;
                }
            }
            m = fmaxf(m, __shfl_xor_sync(0xffffffffu, m, 1));
            float sum = 0.f;
            c = 0;
            for (int ib = 0; ib < nki; ib++) {
                #pragma unroll
                for (int j = 0; j < 14; j++) {
                    float e = fexp(__half2float(Srow[c]) - m);
                    sum += e;
                    Srow[c] = __float2half(e);
                    c++;
                }
            }
            sum += __shfl_xor_sync(0xffffffffu, sum, 1);
            inv = 1.0f / sum;
        }
        __syncwarp();

        // ---------- O = P @ V ----------
        float oacc[8][4];
        #pragma unroll
        for (int i = 0; i < 8; i++)
            #pragma unroll
            for (int j = 0; j < 4; j++) oacc[i][j] = 0.f;
        #pragma unroll 2
        for (int kt = 0; kt < 14; kt++) {
            uint32_t Pf[4];
            ldsm4(Pf, sbase_w + (uint32_t)(a_row * 232 + kt * 16 + a_k) * 2);
            #pragma unroll
            for (int nd = 0; nd < 4; nd++) {
                uint32_t Vf[4];
                ldsm4(Vf, smemb + OFF_V +
                      (uint32_t)((nd * 16 + b_row) * 232 + kt * 16 + b_k) * 2);
                mma16816_h(oacc[nd * 2 + 0], Pf, &Vf[0]);
                mma16816_h(oacc[nd * 2 + 1], Pf, &Vf[2]);
            }
        }

        {
            int r0 = lane >> 2;
            float inv0 = __shfl_sync(0xffffffffu, inv, r0 * 2);
            float inv1 = __shfl_sync(0xffffffffu, inv, (r0 + 8) * 2);
            int g0 = row0 + r0, g1 = g0 + 8;
            int colb = (lane & 3) * 2;
            #pragma unroll
            for (int nt = 0; nt < 8; nt++) {
                int col = nt * 8 + colb;
                if (g0 < 196)
                    *(__half2*)(outh + obase + (size_t)g0 * 768 + col) =
                        __floats2half2_rn(oacc[nt][0] * inv0, oacc[nt][1] * inv0);
                if (g1 < 196)
                    *(__half2*)(outh + obase + (size_t)g1 * 768 + col) =
                        __floats2half2_rn(oacc[nt][2] * inv1, oacc[nt][3] * inv1);
            }
        }
    }
}

// ---------------------------------------------------------------------------
// PERSISTENT single-term fp16 GEMM: grid = 296 CTAs (2/SM), each loops over
// 128x128 tiles.  BK=64, 3 stages, one barrier per K-iter.  Next tile's
// prologue is issued BEFORE this tile's epilogue so stores overlap loads.
// EPI 0: qkv  — bias + scatter to g_qkv_h (fp16)
// EPI 1: proj — unpartition + residual -> fp32
// EPI 2: mlp1 — gelu -> fp16
// EPI 3: mlp2 — residual -> fp32 out
// ---------------------------------------------------------------------------
#define ROWE 72                         // 64 + 8 pad halves per row
#define HTILE_E (128 * ROWE)            // 9216 halves per operand tile
#define HSTAGE_E (2 * HTILE_E)          // A + B
#define HSTAGES 3
#define HGEMM_SMEM (HSTAGES * HSTAGE_E * 2)   // 110592 B
#define GEMM_GRID 296

template <int EPI>
__global__ __launch_bounds__(256, 2)
void hgemm(const __half* __restrict__ A, const __half* __restrict__ B,
           const float* __restrict__ bias, float* __restrict__ Cf,
           __half* __restrict__ Ch, const float* __restrict__ extra,
           int M, int N, int K) {
    extern __shared__ __align__(16) __half smh[];
    uint32_t smemb = smem_u32(smh);

    int tid = threadIdx.x;
    int lane = tid & 31, warp = tid >> 5;
    int wm = warp & 1, wn = warp >> 1;

    int lrow = tid >> 1;
    int c4   = (tid & 1) * 4;
    uint32_t sbase = (uint32_t)(lrow * ROWE + c4 * 8) * 2;

    int a_row = (lane & 7) + ((lane >> 3) & 1) * 8;
    int a_k   = (lane >> 4) * 8;
    int b_row = (lane & 7) + (lane >> 4) * 8;
    int b_k   = ((lane >> 3) & 1) * 8;

    const int nbn = N >> 7;
    const int nbm = (M + 127) >> 7;
    const int ntiles = nbm * nbn;
    const int nt = K / 64;

    // tile-pointer helper state (computed per tile)
    int tile = blockIdx.x;
    if (tile >= ntiles) return;

    auto tile_ptrs = [&](int tl, const char*& pA, const char*& pB,
                         uint32_t& szA, int& bm, int& bn) {
        bn = (tl % nbn) * 128;
        bm = (tl / nbn) * 128;
        int rowA = bm + lrow; bool va = rowA < M;
        int rowB = bn + lrow;
        pA = (const char*)(A + (size_t)(va ? rowA : 0) * K) + c4 * 16;
        pB = (const char*)(B + (size_t)rowB * K) + c4 * 16;
        szA = va ? 16u : 0u;
    };

    const char *pA, *pB; uint32_t szA; int bm, bn;
    tile_ptrs(tile, pA, pB, szA, bm, bn);

    // prologue for first tile: stages 0,1
    #pragma unroll
    for (int ps = 0; ps < HSTAGES - 1; ps++) {
        uint32_t s0 = smemb + (uint32_t)ps * (HSTAGE_E * 2) + sbase;
        uint32_t kb = (uint32_t)ps * 128;
        #pragma unroll
        for (int c = 0; c < 4; c++) {
            cp_async16(s0 + c * 16, pA + kb + c * 16, szA);
            cp_async16(s0 + HTILE_E * 2 + c * 16, pB + kb + c * 16, 16);
        }
        cp_commit();
    }

    for (; tile < ntiles; tile += GEMM_GRID) {
        float acc[4][4][4];
        #pragma unroll
        for (int i = 0; i < 4; i++)
            #pragma unroll
            for (int j = 0; j < 4; j++)
                #pragma unroll
                for (int k = 0; k < 4; k++) acc[i][j][k] = 0.f;

        for (int t = 0; t < nt; t++) {
            cp_wait<1>();
            __syncthreads();

            int tl = t + HSTAGES - 1;
            if (tl < nt) {
                uint32_t s0 = smemb + (uint32_t)(tl % HSTAGES) * (HSTAGE_E * 2) + sbase;
                uint32_t kb = (uint32_t)tl * 128;
                #pragma unroll
                for (int c = 0; c < 4; c++) {
                    cp_async16(s0 + c * 16, pA + kb + c * 16, szA);
                    cp_async16(s0 + HTILE_E * 2 + c * 16, pB + kb + c * 16, 16);
                }
                cp_commit();
            } else {
                cp_commit();   // lockstep for cp_wait<1>
            }

            uint32_t st = smemb + (uint32_t)(t % HSTAGES) * (HSTAGE_E * 2);
            #pragma unroll
            for (int ks = 0; ks < 64; ks += 16) {
                uint32_t Bf[8], Afr[16];
                {
                    uint32_t r0 = (uint32_t)((wn * 32 + b_row) * ROWE + ks + b_k) * 2;
                    uint32_t r1 = (uint32_t)((wn * 32 + 16 + b_row) * ROWE + ks + b_k) * 2;
                    ldsm4(Bf + 0, st + (uint32_t)(HTILE_E) * 2 + r0);
                    ldsm4(Bf + 4, st + (uint32_t)(HTILE_E) * 2 + r1);
                }
                #pragma unroll
                for (int mi = 0; mi < 4; mi++) {
                    uint32_t ra = (uint32_t)((wm * 64 + mi * 16 + a_row) * ROWE + ks + a_k) * 2;
                    ldsm4(&Afr[mi * 4], st + ra);
                }
                #pragma unroll
                for (int mi = 0; mi < 4; mi++)
                    #pragma unroll
                    for (int nj = 0; nj < 4; nj++)
                        mma16816_h(acc[mi][nj], &Afr[mi * 4], &Bf[nj * 2]);
            }
        }

        // all warps done reading smem for this tile
        __syncthreads();

        // issue next tile's prologue NOW so loads overlap the epilogue stores
        int ntile = tile + GEMM_GRID;
        if (ntile < ntiles) {
            tile_ptrs(ntile, pA, pB, szA, bm, bn);
            // NOTE: bm/bn now refer to next tile; save current for epilogue first
        }
        int ebm = (tile / nbn) * 128, ebn = (tile % nbn) * 128;
        if (ntile < ntiles) {
            #pragma unroll
            for (int ps = 0; ps < HSTAGES - 1; ps++) {
                uint32_t s0 = smemb + (uint32_t)ps * (HSTAGE_E * 2) + sbase;
                uint32_t kb = (uint32_t)ps * 128;
                #pragma unroll
                for (int c = 0; c < 4; c++) {
                    cp_async16(s0 + c * 16, pA + kb + c * 16, szA);
                    cp_async16(s0 + HTILE_E * 2 + c * 16, pB + kb + c * 16, 16);
                }
                cp_commit();
            }
        }

        // ---------------- epilogue for current tile ----------------
        #pragma unroll
        for (int mi = 0; mi < 4; mi++) {
            int rb = ebm + wm * 64 + mi * 16 + (lane >> 2);
            #pragma unroll
            for (int hf = 0; hf < 2; hf++) {
                int r = rb + hf * 8;
                if (r >= M) continue;
                int win = 0, n = 0;
                if (EPI == 0 || EPI == 1) { win = r / 196; n = r % 196; }
                bool pvalid = true; size_t pixbase = 0;
                if (EPI == 1) {
                    int b = win / 25, wi = (win % 25) / 5, wj = win % 5;
                    int ph = wi * 14 + n / 14, pw = wj * 14 + n % 14;
                    pvalid = (ph < 64 && pw < 64);
                    pixbase = ((size_t)((b * 64 + ph) * 64 + pw)) * 768;
                }
                #pragma unroll
                for (int nj = 0; nj < 4; nj++) {
                    float v0 = acc[mi][nj][hf * 2 + 0];
                    float v1 = acc[mi][nj][hf * 2 + 1];
                    int col = ebn + wn * 32 + nj * 8 + (lane & 3) * 2;
                    v0 += bias[col]; v1 += bias[col + 1];
                    if (EPI == 0) {
                        int which = col / 768;
                        int rem = col - which * 768;
                        int hh = rem >> 6, d = rem & 63;
                        size_t base = ((((size_t)which * NBH) + (size_t)win * 12 + hh)
                                       * NTOK + n) * 64 + d;
                        *(__half2*)&Ch[base] = __floats2half2_rn(v0, v1);
                    } else if (EPI == 1) {
                        if (pvalid) {
                            size_t idx = pixbase + col;
                            float2 e = *(const float2*)(extra + idx);
                            *(float2*)&Cf[idx] = make_float2(v0 + e.x, v1 + e.y);
                        }
                    } else if (EPI == 2) {
                        size_t idx = (size_t)r * N + col;
                        *(__half2*)(Ch + idx) =
                            __floats2half2_rn(gelu_exact(v0), gelu_exact(v1));
                    } else {
                        size_t idx = (size_t)r * N + col;
                        float2 e = *(const float2*)(extra + idx);
                        *(float2*)&Cf[idx] = make_float2(v0 + e.x, v1 + e.y);
                    }
                }
            }
        }
    }
}

// ---------------------------------------------------------------------------
// Launch
// ---------------------------------------------------------------------------
static float* sym_f(const void* s) { void* p = nullptr; cudaGetSymbolAddress(&p, s); return (float*)p; }
static __half* sym_h(const void* s) { void* p = nullptr; cudaGetSymbolAddress(&p, s); return (__half*)p; }

extern "C" void kernel_launch(void* const* d_in, const int* in_sizes, int n_in,
                              void* d_out, int out_size) {
    const float* x     = (const float*)d_in[0];
    const float* n1g   = (const float*)d_in[1];
    const float* n1b   = (const float*)d_in[2];
    const float* qkvw  = (const float*)d_in[3];
    const float* qkvb  = (const float*)d_in[4];
    const float* projw = (const float*)d_in[5];
    const float* projb = (const float*)d_in[6];
    const float* rph   = (const float*)d_in[7];
    const float* rpw   = (const float*)d_in[8];
    const float* n2g   = (const float*)d_in[9];
    const float* n2b   = (const float*)d_in[10];
    const float* w1    = (const float*)d_in[11];
    const float* b1    = (const float*)d_in[12];
    const float* w2    = (const float*)d_in[13];
    const float* b2    = (const float*)d_in[14];
    float* out = (float*)d_out;

    float* p_x1   = sym_f(g_x1);
    __half *qkvh = sym_h(g_qkv_h);
    __half *winh = sym_h(g_win_h);
    __half *atth = sym_h(g_att_h);
    __half *ln2h = sym_h(g_ln2_h);
    __half *mlph = sym_h(g_mlp_h);
    __half *qwh  = sym_h(g_qkvwt_h);
    __half *pwh  = sym_h(g_projwt_h);
    __half *w1h  = sym_h(g_w1t_h);
    __half *w2h  = sym_h(g_w2t_h);

    cudaFuncSetAttribute(attn_tc_kernel, cudaFuncAttributeMaxDynamicSharedMemorySize,
                         ATC_SMEM);
    cudaFuncSetAttribute(hgemm<0>, cudaFuncAttributeMaxDynamicSharedMemorySize, HGEMM_SMEM);
    cudaFuncSetAttribute(hgemm<1>, cudaFuncAttributeMaxDynamicSharedMemorySize, HGEMM_SMEM);
    cudaFuncSetAttribute(hgemm<2>, cudaFuncAttributeMaxDynamicSharedMemorySize, HGEMM_SMEM);
    cudaFuncSetAttribute(hgemm<3>, cudaFuncAttributeMaxDynamicSharedMemorySize, HGEMM_SMEM);

    // 0) weight transposes -> fp16 [N,K]
    tsplit_h_kernel<<<dim3(2304 / 32, 768 / 32), 256>>>(qkvw, qwh, 768, 2304);
    tsplit_h_kernel<<<dim3(768 / 32, 768 / 32), 256>>>(projw, pwh, 768, 768);
    tsplit_h_kernel<<<dim3(3072 / 32, 768 / 32), 256>>>(w1, w1h, 768, 3072);
    tsplit_h_kernel<<<dim3(768 / 32, 3072 / 32), 256>>>(w2, w2h, 3072, 768);

    // 1) LN1 + window partition -> fp16
    ln_h_kernel<<<TOKS, 256>>>(x, n1g, n1b, winh, 1);

    // 2) QKV GEMM (fp16, persistent) -> fp16 q/k/v scatter
    hgemm<0><<<GEMM_GRID, 256, HGEMM_SMEM>>>(
        winh, qwh, qkvb, nullptr, qkvh, nullptr, TOKS, 2304, 768);

    // 3) tensor-core attention with fused rel-pos bias -> fp16
    attn_tc_kernel<<<NBH, ATHREADS, ATC_SMEM>>>(qkvh, rph, rpw, atth);

    // 4) proj GEMM (persistent) + unpartition + residual -> fp32 x1
    hgemm<1><<<GEMM_GRID, 256, HGEMM_SMEM>>>(
        atth, pwh, projb, p_x1, nullptr, x, TOKS, 768, 768);

    // 5) LN2 -> fp16
    ln_h_kernel<<<PIX, 256>>>(p_x1, n2g, n2b, ln2h, 0);

    // 6) MLP fc1 (persistent) + GELU -> fp16
    hgemm<2><<<GEMM_GRID, 256, HGEMM_SMEM>>>(
        ln2h, w1h, b1, nullptr, mlph, nullptr, PIX, 3072, 768);

    // 7) MLP fc2 (persistent) + residual -> final fp32 output
    hgemm<3><<<GEMM_GRID, 256, HGEMM_SMEM>>>(
        mlph, w2h, b2, out, nullptr, p_x1, PIX, 768, 3072);

    (void)in_sizes; (void)n_in; (void)out_size;
}

// round 15
// speedup vs baseline: 1.0238x; 1.0238x over previous
#include <cuda_runtime.h>
#include <cuda_fp16.h>
#include <math.h>
#include <stdint.h>

// ---------------------------------------------------------------------------
// Problem constants
// ---------------------------------------------------------------------------
#define TOKS 19600
#define PIX  16384
#define NBH  1200
#define NTOK 196

// ---------------------------------------------------------------------------
// Scratch (static __device__ arrays; no allocation anywhere)
// ---------------------------------------------------------------------------
__device__ float g_x1  [16384u * 768u];             // residual-1 (fp32)

__device__ __align__(256) __half g_qkv_h[3u * 1200u * 196u * 64u]; // [w][bh][n][d]
__device__ __align__(256) __half g_win_h[19600u * 768u];   // LN1+partition
__device__ __align__(256) __half g_att_h[19600u * 768u];
__device__ __align__(256) __half g_ln2_h[16384u * 768u];
__device__ __align__(256) __half g_mlp_h[16384u * 3072u];
// transposed (N-major, K contiguous) fp16 weights
__device__ __align__(256) __half g_qkvwt_h[2304u * 768u];
__device__ __align__(256) __half g_projwt_h[768u * 768u];
__device__ __align__(256) __half g_w1t_h[3072u * 768u];
__device__ __align__(256) __half g_w2t_h[768u * 3072u];

// ---------------------------------------------------------------------------
// PTX helpers — sm_80-era features only (harness PTX pass targets plain
// sm_103 which rejects tcgen05/TMEM; mma.sync/ldmatrix/cp.async are fine).
// ---------------------------------------------------------------------------
__device__ __forceinline__ uint32_t smem_u32(const void* p) {
    uint32_t a;
    asm("{ .reg .u64 t; cvta.to.shared.u64 t, %1; cvt.u32.u64 %0, t; }"
        : "=r"(a) : "l"(p));
    return a;
}
__device__ __forceinline__ void cp_async16(uint32_t s, const void* g, uint32_t sz) {
    asm volatile("cp.async.cg.shared.global [%0], [%1], 16, %2;"
                 :: "r"(s), "l"(g), "r"(sz) : "memory");
}
__device__ __forceinline__ void cp_commit() {
    asm volatile("cp.async.commit_group;" ::: "memory");
}
template <int N> __device__ __forceinline__ void cp_wait() {
    asm volatile("cp.async.wait_group %0;" :: "n"(N) : "memory");
}
__device__ __forceinline__ void ldsm4(uint32_t* r, uint32_t addr) {
    asm volatile("ldmatrix.sync.aligned.m8n8.x4.shared.b16 {%0,%1,%2,%3}, [%4];"
                 : "=r"(r[0]), "=r"(r[1]), "=r"(r[2]), "=r"(r[3]) : "r"(addr));
}
__device__ __forceinline__ void mma16816_h(float* c, const uint32_t* a,
                                           const uint32_t* b) {
    asm volatile(
        "mma.sync.aligned.m16n8k16.row.col.f32.f16.f16.f32 "
        "{%0,%1,%2,%3}, {%4,%5,%6,%7}, {%8,%9}, {%0,%1,%2,%3};"
        : "+f"(c[0]), "+f"(c[1]), "+f"(c[2]), "+f"(c[3])
        : "r"(a[0]), "r"(a[1]), "r"(a[2]), "r"(a[3]), "r"(b[0]), "r"(b[1]));
}
__device__ __forceinline__ float gelu_exact(float x) {
    return 0.5f * x * (1.0f + erff(x * 0.70710678118654752440f));
}
// FMA-pipe exp (avoids the 0.5/cyc/SM MUFU bottleneck). Valid for x <= 0,
// rel err ~4e-5.
__device__ __forceinline__ float fexp(float x) {
    x = fmaxf(x, -80.0f);
    float y = x * 1.44269504f;
    float t = __fadd_rn(y, 12582912.0f);
    int ni = __float_as_int(t) - 0x4B400000;
    float f = __fsub_rn(y, __fsub_rn(t, 12582912.0f));
    float p = 0.009618130f;
    p = fmaf(p, f, 0.055504110f);
    p = fmaf(p, f, 0.240226507f);
    p = fmaf(p, f, 0.693147181f);
    p = fmaf(p, f, 1.0f);
    return __int_as_float(__float_as_int(p) + (ni << 23));
}

// ---------------------------------------------------------------------------
// LN (+ optional window-partition gather) -> fp16
// ---------------------------------------------------------------------------
__global__ void ln_h_kernel(const float* __restrict__ in,
                            const float* __restrict__ gamma,
                            const float* __restrict__ beta,
                            __half* __restrict__ oh, int partition) {
    __shared__ float red_s[8], red_q[8];
    int r = blockIdx.x, t = threadIdx.x;
    size_t dst = (size_t)r * 768;
    const float* src;
    if (partition) {
        int wid = r / 196, n = r % 196;
        int b = wid / 25, wi = (wid % 25) / 5, wj = wid % 5;
        int hh = wi * 14 + n / 14, ww = wj * 14 + n % 14;
        if (hh >= 64 || ww >= 64) {
            __half z = __float2half(0.0f);
            for (int c = t; c < 768; c += 256) oh[dst + c] = z;
            return;
        }
        src = in + ((size_t)((b * 64 + hh) * 64 + ww)) * 768;
    } else {
        src = in + (size_t)r * 768;
    }
    float v0 = src[t], v1 = src[t + 256], v2 = src[t + 512];
    float s = v0 + v1 + v2, q = v0 * v0 + v1 * v1 + v2 * v2;
    #pragma unroll
    for (int off = 16; off > 0; off >>= 1) {
        s += __shfl_xor_sync(0xffffffffu, s, off);
        q += __shfl_xor_sync(0xffffffffu, q, off);
    }
    int warp = t >> 5, lane = t & 31;
    if (lane == 0) { red_s[warp] = s; red_q[warp] = q; }
    __syncthreads();
    float st = 0.f, qt = 0.f;
    #pragma unroll
    for (int i = 0; i < 8; i++) { st += red_s[i]; qt += red_q[i]; }
    float mean = st * (1.0f / 768.0f);
    float var  = qt * (1.0f / 768.0f) - mean * mean;
    float rstd = rsqrtf(var + 1e-5f);
    #pragma unroll
    for (int k = 0; k < 3; k++) {
        int c = t + k * 256;
        float vv = (k == 0 ? v0 : (k == 1 ? v1 : v2));
        oh[dst + c] = __float2half((vv - mean) * rstd * gamma[c] + beta[c]);
    }
}

// ---------------------------------------------------------------------------
// Merged weight transpose: all 4 weights in ONE launch.
// Block ranges: [0,1728) qkv  [1728,2304) proj  [2304,4608) w1  [4608,6912) w2
// Inner code identical to the old tsplit_h_kernel (numerics unchanged).
// ---------------------------------------------------------------------------
__global__ void tsplit_all_kernel(const float* __restrict__ Wq,
                                  const float* __restrict__ Wp,
                                  const float* __restrict__ W1,
                                  const float* __restrict__ W2,
                                  __half* __restrict__ Tq,
                                  __half* __restrict__ Tp,
                                  __half* __restrict__ T1,
                                  __half* __restrict__ T2) {
    __shared__ float tile[32][33];
    int b = blockIdx.x;
    const float* W; __half* T; int Kd, Nd, bx;
    if (b < 1728)        { W = Wq; T = Tq; Kd = 768;  Nd = 2304; bx = b; }
    else if (b < 2304)   { W = Wp; T = Tp; Kd = 768;  Nd = 768;  bx = b - 1728; }
    else if (b < 4608)   { W = W1; T = T1; Kd = 768;  Nd = 3072; bx = b - 2304; }
    else                 { W = W2; T = T2; Kd = 3072; Nd = 768;  bx = b - 4608; }
    int nbx = Nd / 32;
    int n0 = (bx % nbx) * 32, k0 = (bx / nbx) * 32;
    int tx = threadIdx.x & 31, ty = threadIdx.x >> 5;
    #pragma unroll
    for (int i = 0; i < 4; i++)
        tile[ty + i * 8][tx] = W[(size_t)(k0 + ty + i * 8) * Nd + n0 + tx];
    __syncthreads();
    #pragma unroll
    for (int i = 0; i < 4; i++) {
        int n = n0 + ty + i * 8, k = k0 + tx;
        T[(size_t)n * Kd + k] = __float2half(tile[tx][ty + i * 8]);
    }
}

// ---------------------------------------------------------------------------
// Tensor-core attention, 13 warps, one strip per warp, fused rel-pos bias
// with k-major broadcast mapping (unchanged from R13 — the 1475us build).
// ---------------------------------------------------------------------------
#define ATHREADS 416
#define OFF_Q 0
#define OFF_K 29952
#define OFF_V 62208
#define OFF_S 91904
#define OFF_RT (OFF_S + 13 * 7424)          // 188416: rel tables 2 x 27x64 f32
#define OFF_RH (OFF_RT + 13824)             // 202240: relh 196x14 f32
#define OFF_RW (OFF_RH + 10976)             // 213216: relw 196x14 f32
#define ATC_SMEM (OFF_RW + 10976)           // 224192 B

__global__ __launch_bounds__(ATHREADS)
void attn_tc_kernel(const __half* __restrict__ qkv,
                    const float* __restrict__ rph,
                    const float* __restrict__ rpw,
                    __half* __restrict__ outh) {
    extern __shared__ char asmem[];
    uint32_t smemb = smem_u32(asmem);
    __half* Qs = (__half*)(asmem + OFF_Q);   // stride 72
    __half* Ks = (__half*)(asmem + OFF_K);   // stride 72
    __half* Vt = (__half*)(asmem + OFF_V);   // stride 232, [ch][tok]
    float* RTh = (float*)(asmem + OFF_RT);          // 27x64
    float* RTw = (float*)(asmem + OFF_RT + 6912);   // 27x64
    float* RelHs = (float*)(asmem + OFF_RH);        // [196][14]
    float* RelWs = (float*)(asmem + OFF_RW);        // [196][14]

    int bh = blockIdx.x;
    int tid = threadIdx.x, warp = tid >> 5, lane = tid & 31;
    const __half* qp = qkv + ((size_t)0 * NBH + bh) * NTOK * 64;
    const __half* kp = qkv + ((size_t)1 * NBH + bh) * NTOK * 64;
    const __half* vp = qkv + ((size_t)2 * NBH + bh) * NTOK * 64;

    const uint4 z4 = make_uint4(0, 0, 0, 0);
    for (int idx = tid; idx < 208 * 8; idx += ATHREADS) {
        int row = idx >> 3, c8 = (idx & 7) * 8;
        uint4 v = (row < 196) ? *(const uint4*)(qp + row * 64 + c8) : z4;
        *(uint4*)(Qs + row * 72 + c8) = v;
    }
    for (int idx = tid; idx < 224 * 8; idx += ATHREADS) {
        int row = idx >> 3, c8 = (idx & 7) * 8;
        uint4 v = (row < 196) ? *(const uint4*)(kp + row * 64 + c8) : z4;
        *(uint4*)(Ks + row * 72 + c8) = v;
    }
    for (int idx = tid; idx < 224 * 64; idx += ATHREADS) {
        int tok = idx >> 6, ch = idx & 63;
        Vt[ch * 232 + tok] = (tok < 196) ? vp[tok * 64 + ch] : __float2half(0.f);
    }
    for (int idx = tid; idx < 27 * 64; idx += ATHREADS) {
        RTh[idx] = rph[idx];
        RTw[idx] = rpw[idx];
    }
    __syncthreads();

    // ---- fused rel-pos bias, k-major mapping (table-row broadcast) ----
    for (int p = tid; p < 14 * 196; p += ATHREADS) {
        int ki = p / 196, row = p % 196;
        const __half* qr = Qs + row * 72;
        const float* rp = RTh + (row / 14 - ki + 13) * 64;
        float s = 0.f;
        #pragma unroll 8
        for (int c = 0; c < 64; c++) s += __half2float(qr[c]) * rp[c];
        RelHs[row * 14 + ki] = s;
    }
    for (int p = tid; p < 14 * 196; p += ATHREADS) {
        int kj = p / 196, rem = p % 196;
        int qj = rem / 14, qi = rem % 14;
        int row = qi * 14 + qj;
        const __half* qr = Qs + row * 72;
        const float* rp = RTw + (qj - kj + 13) * 64;
        float s = 0.f;
        #pragma unroll 8
        for (int c = 0; c < 64; c++) s += __half2float(qr[c]) * rp[c];
        RelWs[row * 14 + kj] = s;
    }
    __syncthreads();

    int win = bh / 12, h = bh % 12;
    size_t obase = (size_t)win * NTOK * 768 + h * 64;

    int a_row = (lane & 7) + ((lane >> 3) & 1) * 8;
    int a_k   = (lane >> 4) * 8;
    int b_row = (lane & 7) + (lane >> 4) * 8;
    int b_k   = ((lane >> 3) & 1) * 8;

    __half* Sp = (__half*)(asmem + OFF_S + warp * 7424);       // [16][232]
    uint32_t sbase_w = smemb + OFF_S + (uint32_t)warp * 7424;

    {
        int strip = warp;               // 0..12, one strip per warp
        int row0 = strip * 16;

        // ---------- S = Q @ K^T ----------
        uint32_t Af[16];
        {
            uint32_t qb = smemb + OFF_Q + (uint32_t)((row0 + a_row) * 72) * 2;
            #pragma unroll
            for (int kt = 0; kt < 4; kt++)
                ldsm4(&Af[kt * 4], qb + (uint32_t)(kt * 16 + a_k) * 2);
        }
        #pragma unroll 2
        for (int n2 = 0; n2 < 14; n2++) {
            uint32_t Bf[16];
            uint32_t kb = smemb + OFF_K + (uint32_t)((n2 * 16 + b_row) * 72) * 2;
            #pragma unroll
            for (int kt = 0; kt < 4; kt++)
                ldsm4(&Bf[kt * 4], kb + (uint32_t)(kt * 16 + b_k) * 2);
            float ac0[4] = {0.f, 0.f, 0.f, 0.f};
            float ac1[4] = {0.f, 0.f, 0.f, 0.f};
            #pragma unroll
            for (int kt = 0; kt < 4; kt++) {
                mma16816_h(ac0, &Af[kt * 4], &Bf[kt * 4]);
                mma16816_h(ac1, &Af[kt * 4], &Bf[kt * 4 + 2]);
            }
            int r = lane >> 2, cc = (lane & 3) * 2;
            int col = n2 * 16 + cc;
            *(__half2*)(Sp + r * 232 + col)           = __floats2half2_rn(ac0[0], ac0[1]);
            *(__half2*)(Sp + (r + 8) * 232 + col)     = __floats2half2_rn(ac0[2], ac0[3]);
            *(__half2*)(Sp + r * 232 + col + 8)       = __floats2half2_rn(ac1[0], ac1[1]);
            *(__half2*)(Sp + (r + 8) * 232 + col + 8) = __floats2half2_rn(ac1[2], ac1[3]);
        }
        __syncwarp();

        // ---------- softmax: 2 lanes/row, register-hoisted bias ----------
        float inv;
        {
            int srow = lane >> 1, half_ = lane & 1;
            int qrow = row0 + srow;
            int rr = qrow < 196 ? qrow : 195;
            const float* RH = RelHs + rr * 14;
            const float* RW = RelWs + rr * 14;
            float rwv[14];
            #pragma unroll
            for (int j = 0; j < 14; j++) rwv[j] = RW[j];
            __half* Srow = Sp + srow * 232 + half_ * 112;
            int ki0 = half_ * 8;
            int nki = half_ ? 6 : 8;        // valid cols: 112 or 84
            float m = -1e30f;
            int c = 0;
            for (int ib = 0; ib < nki; ib++) {
                float rh = RH[ki0 + ib];
                #pragma unroll
                for (int j = 0; j < 14; j++) {
                    float v = __half2float(Srow[c]) * 0.125f + rh + rwv[j];
                    Srow[c] = __float2half(v);
                    m = fmaxf(m, v);
                    c++;
                }
            }
            m = fmaxf(m, __shfl_xor_sync(0xffffffffu, m, 1));
            float sum = 0.f;
            c = 0;
            for (int ib = 0; ib < nki; ib++) {
                #pragma unroll
                for (int j = 0; j < 14; j++) {
                    float e = fexp(__half2float(Srow[c]) - m);
                    sum += e;
                    Srow[c] = __float2half(e);
                    c++;
                }
            }
            sum += __shfl_xor_sync(0xffffffffu, sum, 1);
            inv = 1.0f / sum;
        }
        __syncwarp();

        // ---------- O = P @ V ----------
        float oacc[8][4];
        #pragma unroll
        for (int i = 0; i < 8; i++)
            #pragma unroll
            for (int j = 0; j < 4; j++) oacc[i][j] = 0.f;
        #pragma unroll 2
        for (int kt = 0; kt < 14; kt++) {
            uint32_t Pf[4];
            ldsm4(Pf, sbase_w + (uint32_t)(a_row * 232 + kt * 16 + a_k) * 2);
            #pragma unroll
            for (int nd = 0; nd < 4; nd++) {
                uint32_t Vf[4];
                ldsm4(Vf, smemb + OFF_V +
                      (uint32_t)((nd * 16 + b_row) * 232 + kt * 16 + b_k) * 2);
                mma16816_h(oacc[nd * 2 + 0], Pf, &Vf[0]);
                mma16816_h(oacc[nd * 2 + 1], Pf, &Vf[2]);
            }
        }

        {
            int r0 = lane >> 2;
            float inv0 = __shfl_sync(0xffffffffu, inv, r0 * 2);
            float inv1 = __shfl_sync(0xffffffffu, inv, (r0 + 8) * 2);
            int g0 = row0 + r0, g1 = g0 + 8;
            int colb = (lane & 3) * 2;
            #pragma unroll
            for (int nt = 0; nt < 8; nt++) {
                int col = nt * 8 + colb;
                if (g0 < 196)
                    *(__half2*)(outh + obase + (size_t)g0 * 768 + col) =
                        __floats2half2_rn(oacc[nt][0] * inv0, oacc[nt][1] * inv0);
                if (g1 < 196)
                    *(__half2*)(outh + obase + (size_t)g1 * 768 + col) =
                        __floats2half2_rn(oacc[nt][2] * inv1, oacc[nt][3] * inv1);
            }
        }
    }
}

// ---------------------------------------------------------------------------
// Single-term fp16 GEMM (EXACT R13 config — the 1475us build): 8 warps,
// warp tile 64x32, 2 CTAs/SM, BK=64, 3 stages, one barrier per K-iter.
// EPI 0: qkv  — bias + scatter to g_qkv_h (fp16)
// EPI 1: proj — unpartition + residual -> fp32
// EPI 2: mlp1 — gelu -> fp16
// EPI 3: mlp2 — residual -> fp32 out
// ---------------------------------------------------------------------------
#define ROWE 72                         // 64 + 8 pad halves per row
#define HTILE_E (128 * ROWE)            // 9216 halves per operand tile
#define HSTAGE_E (2 * HTILE_E)          // A + B
#define HSTAGES 3
#define HGEMM_SMEM (HSTAGES * HSTAGE_E * 2)   // 110592 B

template <int EPI>
__global__ __launch_bounds__(256, 2)
void hgemm(const __half* __restrict__ A, const __half* __restrict__ B,
           const float* __restrict__ bias, float* __restrict__ Cf,
           __half* __restrict__ Ch, const float* __restrict__ extra,
           int M, int N, int K) {
    extern __shared__ __align__(16) __half smh[];
    uint32_t smemb = smem_u32(smh);

    int tid = threadIdx.x;
    int bm = blockIdx.y * 128, bn = blockIdx.x * 128;
    int lane = tid & 31, warp = tid >> 5;
    int wm = warp & 1, wn = warp >> 1;

    // loader: thread owns half a row (64B = 4 x 16B chunks) per tile
    int lrow = tid >> 1;
    int c4   = (tid & 1) * 4;           // chunk base: 0 or 4 (of 8)
    uint32_t sbase = (uint32_t)(lrow * ROWE + c4 * 8) * 2;
    int rowA = bm + lrow; bool va = rowA < M;
    int rowB = bn + lrow;
    const char* pA = (const char*)(A + (size_t)(va ? rowA : 0) * K) + c4 * 16;
    const char* pB = (const char*)(B + (size_t)rowB * K) + c4 * 16;
    uint32_t szA = va ? 16u : 0u;

    int a_row = (lane & 7) + ((lane >> 3) & 1) * 8;
    int a_k   = (lane >> 4) * 8;
    int b_row = (lane & 7) + (lane >> 4) * 8;
    int b_k   = ((lane >> 3) & 1) * 8;

    float acc[4][4][4];
    #pragma unroll
    for (int i = 0; i < 4; i++)
        #pragma unroll
        for (int j = 0; j < 4; j++)
            #pragma unroll
            for (int k = 0; k < 4; k++) acc[i][j][k] = 0.f;

    const int nt = K / 64;

    // prologue: stages 0,1
    #pragma unroll
    for (int ps = 0; ps < HSTAGES - 1; ps++) {
        uint32_t s0 = smemb + (uint32_t)ps * (HSTAGE_E * 2) + sbase;
        uint32_t kb = (uint32_t)ps * 128;
        #pragma unroll
        for (int c = 0; c < 4; c++) {
            cp_async16(s0 + c * 16, pA + kb + c * 16, szA);
            cp_async16(s0 + HTILE_E * 2 + c * 16, pB + kb + c * 16, 16);
        }
        cp_commit();
    }

    for (int t = 0; t < nt; t++) {
        cp_wait<1>();
        __syncthreads();

        int tl = t + HSTAGES - 1;
        if (tl < nt) {
            uint32_t s0 = smemb + (uint32_t)(tl % HSTAGES) * (HSTAGE_E * 2) + sbase;
            uint32_t kb = (uint32_t)tl * 128;
            #pragma unroll
            for (int c = 0; c < 4; c++) {
                cp_async16(s0 + c * 16, pA + kb + c * 16, szA);
                cp_async16(s0 + HTILE_E * 2 + c * 16, pB + kb + c * 16, 16);
            }
            cp_commit();
        } else {
            cp_commit();   // lockstep for cp_wait<1>
        }

        uint32_t st = smemb + (uint32_t)(t % HSTAGES) * (HSTAGE_E * 2);
        #pragma unroll
        for (int ks = 0; ks < 64; ks += 16) {
            uint32_t Bf[8], Afr[16];
            {
                uint32_t r0 = (uint32_t)((wn * 32 + b_row) * ROWE + ks + b_k) * 2;
                uint32_t r1 = (uint32_t)((wn * 32 + 16 + b_row) * ROWE + ks + b_k) * 2;
                ldsm4(Bf + 0, st + (uint32_t)(HTILE_E) * 2 + r0);
                ldsm4(Bf + 4, st + (uint32_t)(HTILE_E) * 2 + r1);
            }
            #pragma unroll
            for (int mi = 0; mi < 4; mi++) {
                uint32_t ra = (uint32_t)((wm * 64 + mi * 16 + a_row) * ROWE + ks + a_k) * 2;
                ldsm4(&Afr[mi * 4], st + ra);
            }
            #pragma unroll
            for (int mi = 0; mi < 4; mi++)
                #pragma unroll
                for (int nj = 0; nj < 4; nj++)
                    mma16816_h(acc[mi][nj], &Afr[mi * 4], &Bf[nj * 2]);
        }
    }

    // epilogue (no sync needed: each warp reads only its own acc)
    #pragma unroll
    for (int mi = 0; mi < 4; mi++) {
        int rb = bm + wm * 64 + mi * 16 + (lane >> 2);
        #pragma unroll
        for (int hf = 0; hf < 2; hf++) {
            int r = rb + hf * 8;
            if (r >= M) continue;
            int win = 0, n = 0;
            if (EPI == 0 || EPI == 1) { win = r / 196; n = r % 196; }
            bool pvalid = true; size_t pixbase = 0;
            if (EPI == 1) {
                int b = win / 25, wi = (win % 25) / 5, wj = win % 5;
                int ph = wi * 14 + n / 14, pw = wj * 14 + n % 14;
                pvalid = (ph < 64 && pw < 64);
                pixbase = ((size_t)((b * 64 + ph) * 64 + pw)) * 768;
            }
            #pragma unroll
            for (int nj = 0; nj < 4; nj++) {
                float v0 = acc[mi][nj][hf * 2 + 0];
                float v1 = acc[mi][nj][hf * 2 + 1];
                int col = bn + wn * 32 + nj * 8 + (lane & 3) * 2;
                v0 += bias[col]; v1 += bias[col + 1];
                if (EPI == 0) {
                    int which = col / 768;
                    int rem = col - which * 768;
                    int hh = rem >> 6, d = rem & 63;
                    size_t base = ((((size_t)which * NBH) + (size_t)win * 12 + hh)
                                   * NTOK + n) * 64 + d;
                    *(__half2*)&Ch[base] = __floats2half2_rn(v0, v1);
                } else if (EPI == 1) {
                    if (pvalid) {
                        size_t idx = pixbase + col;
                        float2 e = *(const float2*)(extra + idx);
                        *(float2*)&Cf[idx] = make_float2(v0 + e.x, v1 + e.y);
                    }
                } else if (EPI == 2) {
                    size_t idx = (size_t)r * N + col;
                    *(__half2*)(Ch + idx) =
                        __floats2half2_rn(gelu_exact(v0), gelu_exact(v1));
                } else {
                    size_t idx = (size_t)r * N + col;
                    float2 e = *(const float2*)(extra + idx);
                    *(float2*)&Cf[idx] = make_float2(v0 + e.x, v1 + e.y);
                }
            }
        }
    }
}

// ---------------------------------------------------------------------------
// Launch
// ---------------------------------------------------------------------------
static float* sym_f(const void* s) { void* p = nullptr; cudaGetSymbolAddress(&p, s); return (float*)p; }
static __half* sym_h(const void* s) { void* p = nullptr; cudaGetSymbolAddress(&p, s); return (__half*)p; }

extern "C" void kernel_launch(void* const* d_in, const int* in_sizes, int n_in,
                              void* d_out, int out_size) {
    const float* x     = (const float*)d_in[0];
    const float* n1g   = (const float*)d_in[1];
    const float* n1b   = (const float*)d_in[2];
    const float* qkvw  = (const float*)d_in[3];
    const float* qkvb  = (const float*)d_in[4];
    const float* projw = (const float*)d_in[5];
    const float* projb = (const float*)d_in[6];
    const float* rph   = (const float*)d_in[7];
    const float* rpw   = (const float*)d_in[8];
    const float* n2g   = (const float*)d_in[9];
    const float* n2b   = (const float*)d_in[10];
    const float* w1    = (const float*)d_in[11];
    const float* b1    = (const float*)d_in[12];
    const float* w2    = (const float*)d_in[13];
    const float* b2    = (const float*)d_in[14];
    float* out = (float*)d_out;

    float* p_x1   = sym_f(g_x1);
    __half *qkvh = sym_h(g_qkv_h);
    __half *winh = sym_h(g_win_h);
    __half *atth = sym_h(g_att_h);
    __half *ln2h = sym_h(g_ln2_h);
    __half *mlph = sym_h(g_mlp_h);
    __half *qwh  = sym_h(g_qkvwt_h);
    __half *pwh  = sym_h(g_projwt_h);
    __half *w1h  = sym_h(g_w1t_h);
    __half *w2h  = sym_h(g_w2t_h);

    cudaFuncSetAttribute(attn_tc_kernel, cudaFuncAttributeMaxDynamicSharedMemorySize,
                         ATC_SMEM);
    cudaFuncSetAttribute(hgemm<0>, cudaFuncAttributeMaxDynamicSharedMemorySize, HGEMM_SMEM);
    cudaFuncSetAttribute(hgemm<1>, cudaFuncAttributeMaxDynamicSharedMemorySize, HGEMM_SMEM);
    cudaFuncSetAttribute(hgemm<2>, cudaFuncAttributeMaxDynamicSharedMemorySize, HGEMM_SMEM);
    cudaFuncSetAttribute(hgemm<3>, cudaFuncAttributeMaxDynamicSharedMemorySize, HGEMM_SMEM);

    // 0) merged weight transposes -> fp16 [N,K]  (one launch for all four)
    tsplit_all_kernel<<<6912, 256>>>(qkvw, projw, w1, w2, qwh, pwh, w1h, w2h);

    // 1) LN1 + window partition -> fp16
    ln_h_kernel<<<TOKS, 256>>>(x, n1g, n1b, winh, 1);

    // 2) QKV GEMM (fp16) -> fp16 q/k/v scatter
    hgemm<0><<<dim3(2304 / 128, (TOKS + 127) / 128), 256, HGEMM_SMEM>>>(
        winh, qwh, qkvb, nullptr, qkvh, nullptr, TOKS, 2304, 768);

    // 3) tensor-core attention with fused rel-pos bias -> fp16
    attn_tc_kernel<<<NBH, ATHREADS, ATC_SMEM>>>(qkvh, rph, rpw, atth);

    // 4) proj GEMM (fp16) + unpartition + residual -> fp32 x1
    hgemm<1><<<dim3(768 / 128, (TOKS + 127) / 128), 256, HGEMM_SMEM>>>(
        atth, pwh, projb, p_x1, nullptr, x, TOKS, 768, 768);

    // 5) LN2 -> fp16
    ln_h_kernel<<<PIX, 256>>>(p_x1, n2g, n2b, ln2h, 0);

    // 6) MLP fc1 (fp16) + GELU -> fp16
    hgemm<2><<<dim3(3072 / 128, PIX / 128), 256, HGEMM_SMEM>>>(
        ln2h, w1h, b1, nullptr, mlph, nullptr, PIX, 3072, 768);

    // 7) MLP fc2 (fp16) + residual -> final fp32 output
    hgemm<3><<<dim3(768 / 128, PIX / 128), 256, HGEMM_SMEM>>>(
        mlph, w2h, b2, out, nullptr, p_x1, PIX, 768, 3072);

    (void)in_sizes; (void)n_in; (void)out_size;
}

// round 16
// speedup vs baseline: 1.0362x; 1.0121x over previous
#include <cuda_runtime.h>
#include <cuda_fp16.h>
#include <math.h>
#include <stdint.h>

// ---------------------------------------------------------------------------
// Problem constants
// ---------------------------------------------------------------------------
#define TOKS 19600
#define PIX  16384
#define NBH  1200
#define NTOK 196

// ---------------------------------------------------------------------------
// Scratch (static __device__ arrays; no allocation anywhere)
// ---------------------------------------------------------------------------
__device__ float g_x1  [16384u * 768u];             // residual-1 (fp32)

__device__ __align__(256) __half g_qkv_h[3u * 1200u * 196u * 64u]; // [w][bh][n][d]
__device__ __align__(256) __half g_win_h[19600u * 768u];   // LN1+partition
__device__ __align__(256) __half g_att_h[19600u * 768u];
__device__ __align__(256) __half g_ln2_h[16384u * 768u];
__device__ __align__(256) __half g_mlp_h[16384u * 3072u];
// transposed (N-major, K contiguous) fp16 weights
__device__ __align__(256) __half g_qkvwt_h[2304u * 768u];
__device__ __align__(256) __half g_projwt_h[768u * 768u];
__device__ __align__(256) __half g_w1t_h[3072u * 768u];
__device__ __align__(256) __half g_w2t_h[768u * 3072u];

// ---------------------------------------------------------------------------
// PTX helpers — sm_80-era features only (harness PTX pass targets plain
// sm_103 which rejects tcgen05/TMEM; mma.sync/ldmatrix/cp.async are fine).
// ---------------------------------------------------------------------------
__device__ __forceinline__ uint32_t smem_u32(const void* p) {
    uint32_t a;
    asm("{ .reg .u64 t; cvta.to.shared.u64 t, %1; cvt.u32.u64 %0, t; }"
        : "=r"(a) : "l"(p));
    return a;
}
__device__ __forceinline__ void cp_async16(uint32_t s, const void* g, uint32_t sz) {
    asm volatile("cp.async.cg.shared.global [%0], [%1], 16, %2;"
                 :: "r"(s), "l"(g), "r"(sz) : "memory");
}
__device__ __forceinline__ void cp_commit() {
    asm volatile("cp.async.commit_group;" ::: "memory");
}
template <int N> __device__ __forceinline__ void cp_wait() {
    asm volatile("cp.async.wait_group %0;" :: "n"(N) : "memory");
}
__device__ __forceinline__ void ldsm4(uint32_t* r, uint32_t addr) {
    asm volatile("ldmatrix.sync.aligned.m8n8.x4.shared.b16 {%0,%1,%2,%3}, [%4];"
                 : "=r"(r[0]), "=r"(r[1]), "=r"(r[2]), "=r"(r[3]) : "r"(addr));
}
__device__ __forceinline__ void mma16816_h(float* c, const uint32_t* a,
                                           const uint32_t* b) {
    asm volatile(
        "mma.sync.aligned.m16n8k16.row.col.f32.f16.f16.f32 "
        "{%0,%1,%2,%3}, {%4,%5,%6,%7}, {%8,%9}, {%0,%1,%2,%3};"
        : "+f"(c[0]), "+f"(c[1]), "+f"(c[2]), "+f"(c[3])
        : "r"(a[0]), "r"(a[1]), "r"(a[2]), "r"(a[3]), "r"(b[0]), "r"(b[1]));
}
__device__ __forceinline__ float gelu_exact(float x) {
    return 0.5f * x * (1.0f + erff(x * 0.70710678118654752440f));
}
// FMA-pipe exp (avoids the 0.5/cyc/SM MUFU bottleneck). Valid for x <= 0,
// rel err ~4e-5.
__device__ __forceinline__ float fexp(float x) {
    x = fmaxf(x, -80.0f);
    float y = x * 1.44269504f;
    float t = __fadd_rn(y, 12582912.0f);
    int ni = __float_as_int(t) - 0x4B400000;
    float f = __fsub_rn(y, __fsub_rn(t, 12582912.0f));
    float p = 0.009618130f;
    p = fmaf(p, f, 0.055504110f);
    p = fmaf(p, f, 0.240226507f);
    p = fmaf(p, f, 0.693147181f);
    p = fmaf(p, f, 1.0f);
    return __int_as_float(__float_as_int(p) + (ni << 23));
}

// ---------------------------------------------------------------------------
// LN (+ optional window-partition gather) -> fp16
// ---------------------------------------------------------------------------
__global__ void ln_h_kernel(const float* __restrict__ in,
                            const float* __restrict__ gamma,
                            const float* __restrict__ beta,
                            __half* __restrict__ oh, int partition) {
    __shared__ float red_s[8], red_q[8];
    int r = blockIdx.x, t = threadIdx.x;
    size_t dst = (size_t)r * 768;
    const float* src;
    if (partition) {
        int wid = r / 196, n = r % 196;
        int b = wid / 25, wi = (wid % 25) / 5, wj = wid % 5;
        int hh = wi * 14 + n / 14, ww = wj * 14 + n % 14;
        if (hh >= 64 || ww >= 64) {
            __half z = __float2half(0.0f);
            for (int c = t; c < 768; c += 256) oh[dst + c] = z;
            return;
        }
        src = in + ((size_t)((b * 64 + hh) * 64 + ww)) * 768;
    } else {
        src = in + (size_t)r * 768;
    }
    float v0 = src[t], v1 = src[t + 256], v2 = src[t + 512];
    float s = v0 + v1 + v2, q = v0 * v0 + v1 * v1 + v2 * v2;
    #pragma unroll
    for (int off = 16; off > 0; off >>= 1) {
        s += __shfl_xor_sync(0xffffffffu, s, off);
        q += __shfl_xor_sync(0xffffffffu, q, off);
    }
    int warp = t >> 5, lane = t & 31;
    if (lane == 0) { red_s[warp] = s; red_q[warp] = q; }
    __syncthreads();
    float st = 0.f, qt = 0.f;
    #pragma unroll
    for (int i = 0; i < 8; i++) { st += red_s[i]; qt += red_q[i]; }
    float mean = st * (1.0f / 768.0f);
    float var  = qt * (1.0f / 768.0f) - mean * mean;
    float rstd = rsqrtf(var + 1e-5f);
    #pragma unroll
    for (int k = 0; k < 3; k++) {
        int c = t + k * 256;
        float vv = (k == 0 ? v0 : (k == 1 ? v1 : v2));
        oh[dst + c] = __float2half((vv - mean) * rstd * gamma[c] + beta[c]);
    }
}

// ---------------------------------------------------------------------------
// Merged weight transpose: all 4 weights in ONE launch.
// ---------------------------------------------------------------------------
__global__ void tsplit_all_kernel(const float* __restrict__ Wq,
                                  const float* __restrict__ Wp,
                                  const float* __restrict__ W1,
                                  const float* __restrict__ W2,
                                  __half* __restrict__ Tq,
                                  __half* __restrict__ Tp,
                                  __half* __restrict__ T1,
                                  __half* __restrict__ T2) {
    __shared__ float tile[32][33];
    int b = blockIdx.x;
    const float* W; __half* T; int Kd, Nd, bx;
    if (b < 1728)        { W = Wq; T = Tq; Kd = 768;  Nd = 2304; bx = b; }
    else if (b < 2304)   { W = Wp; T = Tp; Kd = 768;  Nd = 768;  bx = b - 1728; }
    else if (b < 4608)   { W = W1; T = T1; Kd = 768;  Nd = 3072; bx = b - 2304; }
    else                 { W = W2; T = T2; Kd = 3072; Nd = 768;  bx = b - 4608; }
    int nbx = Nd / 32;
    int n0 = (bx % nbx) * 32, k0 = (bx / nbx) * 32;
    int tx = threadIdx.x & 31, ty = threadIdx.x >> 5;
    #pragma unroll
    for (int i = 0; i < 4; i++)
        tile[ty + i * 8][tx] = W[(size_t)(k0 + ty + i * 8) * Nd + n0 + tx];
    __syncthreads();
    #pragma unroll
    for (int i = 0; i < 4; i++) {
        int n = n0 + ty + i * 8, k = k0 + tx;
        T[(size_t)n * Kd + k] = __float2half(tile[tx][ty + i * 8]);
    }
}

// ---------------------------------------------------------------------------
// Tensor-core attention, 13 warps, one strip per warp, fused rel-pos bias.
// R16: relpos dots and both softmax passes vectorized (half2 / float2) with
// identical fp32 accumulation order -> numerics preserved.
// ---------------------------------------------------------------------------
#define ATHREADS 416
#define OFF_Q 0
#define OFF_K 29952
#define OFF_V 62208
#define OFF_S 91904
#define OFF_RT (OFF_S + 13 * 7424)          // 188416: rel tables 2 x 27x64 f32
#define OFF_RH (OFF_RT + 13824)             // 202240: relh 196x14 f32
#define OFF_RW (OFF_RH + 10976)             // 213216: relw 196x14 f32
#define ATC_SMEM (OFF_RW + 10976)           // 224192 B

__global__ __launch_bounds__(ATHREADS)
void attn_tc_kernel(const __half* __restrict__ qkv,
                    const float* __restrict__ rph,
                    const float* __restrict__ rpw,
                    __half* __restrict__ outh) {
    extern __shared__ char asmem[];
    uint32_t smemb = smem_u32(asmem);
    __half* Qs = (__half*)(asmem + OFF_Q);   // stride 72
    __half* Ks = (__half*)(asmem + OFF_K);   // stride 72
    __half* Vt = (__half*)(asmem + OFF_V);   // stride 232, [ch][tok]
    float* RTh = (float*)(asmem + OFF_RT);          // 27x64
    float* RTw = (float*)(asmem + OFF_RT + 6912);   // 27x64
    float* RelHs = (float*)(asmem + OFF_RH);        // [196][14]
    float* RelWs = (float*)(asmem + OFF_RW);        // [196][14]

    int bh = blockIdx.x;
    int tid = threadIdx.x, warp = tid >> 5, lane = tid & 31;
    const __half* qp = qkv + ((size_t)0 * NBH + bh) * NTOK * 64;
    const __half* kp = qkv + ((size_t)1 * NBH + bh) * NTOK * 64;
    const __half* vp = qkv + ((size_t)2 * NBH + bh) * NTOK * 64;

    const uint4 z4 = make_uint4(0, 0, 0, 0);
    for (int idx = tid; idx < 208 * 8; idx += ATHREADS) {
        int row = idx >> 3, c8 = (idx & 7) * 8;
        uint4 v = (row < 196) ? *(const uint4*)(qp + row * 64 + c8) : z4;
        *(uint4*)(Qs + row * 72 + c8) = v;
    }
    for (int idx = tid; idx < 224 * 8; idx += ATHREADS) {
        int row = idx >> 3, c8 = (idx & 7) * 8;
        uint4 v = (row < 196) ? *(const uint4*)(kp + row * 64 + c8) : z4;
        *(uint4*)(Ks + row * 72 + c8) = v;
    }
    for (int idx = tid; idx < 224 * 64; idx += ATHREADS) {
        int tok = idx >> 6, ch = idx & 63;
        Vt[ch * 232 + tok] = (tok < 196) ? vp[tok * 64 + ch] : __float2half(0.f);
    }
    for (int idx = tid; idx < 27 * 64; idx += ATHREADS) {
        RTh[idx] = rph[idx];
        RTw[idx] = rpw[idx];
    }
    __syncthreads();

    // ---- fused rel-pos bias, k-major mapping, half2/float2 vectorized ----
    for (int p = tid; p < 14 * 196; p += ATHREADS) {
        int ki = p / 196, row = p % 196;
        const __half2* q2 = (const __half2*)(Qs + row * 72);
        const float2* rp2 = (const float2*)(RTh + (row / 14 - ki + 13) * 64);
        float s = 0.f;
        #pragma unroll 8
        for (int c2 = 0; c2 < 32; c2++) {
            float2 qf = __half22float2(q2[c2]);
            float2 rv = rp2[c2];
            s = fmaf(qf.x, rv.x, s);
            s = fmaf(qf.y, rv.y, s);
        }
        RelHs[row * 14 + ki] = s;
    }
    for (int p = tid; p < 14 * 196; p += ATHREADS) {
        int kj = p / 196, rem = p % 196;
        int qj = rem / 14, qi = rem % 14;
        int row = qi * 14 + qj;
        const __half2* q2 = (const __half2*)(Qs + row * 72);
        const float2* rp2 = (const float2*)(RTw + (qj - kj + 13) * 64);
        float s = 0.f;
        #pragma unroll 8
        for (int c2 = 0; c2 < 32; c2++) {
            float2 qf = __half22float2(q2[c2]);
            float2 rv = rp2[c2];
            s = fmaf(qf.x, rv.x, s);
            s = fmaf(qf.y, rv.y, s);
        }
        RelWs[row * 14 + kj] = s;
    }
    __syncthreads();

    int win = bh / 12, h = bh % 12;
    size_t obase = (size_t)win * NTOK * 768 + h * 64;

    int a_row = (lane & 7) + ((lane >> 3) & 1) * 8;
    int a_k   = (lane >> 4) * 8;
    int b_row = (lane & 7) + (lane >> 4) * 8;
    int b_k   = ((lane >> 3) & 1) * 8;

    __half* Sp = (__half*)(asmem + OFF_S + warp * 7424);       // [16][232]
    uint32_t sbase_w = smemb + OFF_S + (uint32_t)warp * 7424;

    {
        int strip = warp;               // 0..12, one strip per warp
        int row0 = strip * 16;

        // ---------- S = Q @ K^T ----------
        uint32_t Af[16];
        {
            uint32_t qb = smemb + OFF_Q + (uint32_t)((row0 + a_row) * 72) * 2;
            #pragma unroll
            for (int kt = 0; kt < 4; kt++)
                ldsm4(&Af[kt * 4], qb + (uint32_t)(kt * 16 + a_k) * 2);
        }
        #pragma unroll 2
        for (int n2 = 0; n2 < 14; n2++) {
            uint32_t Bf[16];
            uint32_t kb = smemb + OFF_K + (uint32_t)((n2 * 16 + b_row) * 72) * 2;
            #pragma unroll
            for (int kt = 0; kt < 4; kt++)
                ldsm4(&Bf[kt * 4], kb + (uint32_t)(kt * 16 + b_k) * 2);
            float ac0[4] = {0.f, 0.f, 0.f, 0.f};
            float ac1[4] = {0.f, 0.f, 0.f, 0.f};
            #pragma unroll
            for (int kt = 0; kt < 4; kt++) {
                mma16816_h(ac0, &Af[kt * 4], &Bf[kt * 4]);
                mma16816_h(ac1, &Af[kt * 4], &Bf[kt * 4 + 2]);
            }
            int r = lane >> 2, cc = (lane & 3) * 2;
            int col = n2 * 16 + cc;
            *(__half2*)(Sp + r * 232 + col)           = __floats2half2_rn(ac0[0], ac0[1]);
            *(__half2*)(Sp + (r + 8) * 232 + col)     = __floats2half2_rn(ac0[2], ac0[3]);
            *(__half2*)(Sp + r * 232 + col + 8)       = __floats2half2_rn(ac1[0], ac1[1]);
            *(__half2*)(Sp + (r + 8) * 232 + col + 8) = __floats2half2_rn(ac1[2], ac1[3]);
        }
        __syncwarp();

        // ---------- softmax: 2 lanes/row, half2-vectorized passes ----------
        float inv;
        {
            int srow = lane >> 1, half_ = lane & 1;
            int qrow = row0 + srow;
            int rr = qrow < 196 ? qrow : 195;
            const float* RH = RelHs + rr * 14;
            const float* RW = RelWs + rr * 14;
            float rwv[14];
            #pragma unroll
            for (int j = 0; j < 14; j++) rwv[j] = RW[j];
            __half2* S2 = (__half2*)(Sp + srow * 232 + half_ * 112);
            int ki0 = half_ * 8;
            int nki = half_ ? 6 : 8;        // valid cols: 112 or 84
            float m = -1e30f;
            int c2 = 0;
            for (int ib = 0; ib < nki; ib++) {
                float rh = RH[ki0 + ib];
                #pragma unroll
                for (int j2 = 0; j2 < 7; j2++) {
                    float2 f = __half22float2(S2[c2]);
                    float v0 = f.x * 0.125f + rh + rwv[j2 * 2];
                    float v1 = f.y * 0.125f + rh + rwv[j2 * 2 + 1];
                    S2[c2] = __floats2half2_rn(v0, v1);
                    m = fmaxf(m, fmaxf(v0, v1));
                    c2++;
                }
            }
            m = fmaxf(m, __shfl_xor_sync(0xffffffffu, m, 1));
            float sum = 0.f;
            c2 = 0;
            for (int ib = 0; ib < nki; ib++) {
                #pragma unroll
                for (int j2 = 0; j2 < 7; j2++) {
                    float2 f = __half22float2(S2[c2]);
                    float e0 = fexp(f.x - m);
                    float e1 = fexp(f.y - m);
                    sum += e0;
                    sum += e1;
                    S2[c2] = __floats2half2_rn(e0, e1);
                    c2++;
                }
            }
            sum += __shfl_xor_sync(0xffffffffu, sum, 1);
            inv = 1.0f / sum;
        }
        __syncwarp();

        // ---------- O = P @ V ----------
        float oacc[8][4];
        #pragma unroll
        for (int i = 0; i < 8; i++)
            #pragma unroll
            for (int j = 0; j < 4; j++) oacc[i][j] = 0.f;
        #pragma unroll 2
        for (int kt = 0; kt < 14; kt++) {
            uint32_t Pf[4];
            ldsm4(Pf, sbase_w + (uint32_t)(a_row * 232 + kt * 16 + a_k) * 2);
            #pragma unroll
            for (int nd = 0; nd < 4; nd++) {
                uint32_t Vf[4];
                ldsm4(Vf, smemb + OFF_V +
                      (uint32_t)((nd * 16 + b_row) * 232 + kt * 16 + b_k) * 2);
                mma16816_h(oacc[nd * 2 + 0], Pf, &Vf[0]);
                mma16816_h(oacc[nd * 2 + 1], Pf, &Vf[2]);
            }
        }

        {
            int r0 = lane >> 2;
            float inv0 = __shfl_sync(0xffffffffu, inv, r0 * 2);
            float inv1 = __shfl_sync(0xffffffffu, inv, (r0 + 8) * 2);
            int g0 = row0 + r0, g1 = g0 + 8;
            int colb = (lane & 3) * 2;
            #pragma unroll
            for (int nt = 0; nt < 8; nt++) {
                int col = nt * 8 + colb;
                if (g0 < 196)
                    *(__half2*)(outh + obase + (size_t)g0 * 768 + col) =
                        __floats2half2_rn(oacc[nt][0] * inv0, oacc[nt][1] * inv0);
                if (g1 < 196)
                    *(__half2*)(outh + obase + (size_t)g1 * 768 + col) =
                        __floats2half2_rn(oacc[nt][2] * inv1, oacc[nt][3] * inv1);
            }
        }
    }
}

// ---------------------------------------------------------------------------
// Single-term fp16 GEMM (EXACT R13 config — the 1475us build): 8 warps,
// warp tile 64x32, 2 CTAs/SM, BK=64, 3 stages, one barrier per K-iter.
// EPI 0: qkv  — bias + scatter to g_qkv_h (fp16)
// EPI 1: proj — unpartition + residual -> fp32
// EPI 2: mlp1 — gelu -> fp16
// EPI 3: mlp2 — residual -> fp32 out
// ---------------------------------------------------------------------------
#define ROWE 72                         // 64 + 8 pad halves per row
#define HTILE_E (128 * ROWE)            // 9216 halves per operand tile
#define HSTAGE_E (2 * HTILE_E)          // A + B
#define HSTAGES 3
#define HGEMM_SMEM (HSTAGES * HSTAGE_E * 2)   // 110592 B

template <int EPI>
__global__ __launch_bounds__(256, 2)
void hgemm(const __half* __restrict__ A, const __half* __restrict__ B,
           const float* __restrict__ bias, float* __restrict__ Cf,
           __half* __restrict__ Ch, const float* __restrict__ extra,
           int M, int N, int K) {
    extern __shared__ __align__(16) __half smh[];
    uint32_t smemb = smem_u32(smh);

    int tid = threadIdx.x;
    int bm = blockIdx.y * 128, bn = blockIdx.x * 128;
    int lane = tid & 31, warp = tid >> 5;
    int wm = warp & 1, wn = warp >> 1;

    int lrow = tid >> 1;
    int c4   = (tid & 1) * 4;
    uint32_t sbase = (uint32_t)(lrow * ROWE + c4 * 8) * 2;
    int rowA = bm + lrow; bool va = rowA < M;
    int rowB = bn + lrow;
    const char* pA = (const char*)(A + (size_t)(va ? rowA : 0) * K) + c4 * 16;
    const char* pB = (const char*)(B + (size_t)rowB * K) + c4 * 16;
    uint32_t szA = va ? 16u : 0u;

    int a_row = (lane & 7) + ((lane >> 3) & 1) * 8;
    int a_k   = (lane >> 4) * 8;
    int b_row = (lane & 7) + (lane >> 4) * 8;
    int b_k   = ((lane >> 3) & 1) * 8;

    float acc[4][4][4];
    #pragma unroll
    for (int i = 0; i < 4; i++)
        #pragma unroll
        for (int j = 0; j < 4; j++)
            #pragma unroll
            for (int k = 0; k < 4; k++) acc[i][j][k] = 0.f;

    const int nt = K / 64;

    #pragma unroll
    for (int ps = 0; ps < HSTAGES - 1; ps++) {
        uint32_t s0 = smemb + (uint32_t)ps * (HSTAGE_E * 2) + sbase;
        uint32_t kb = (uint32_t)ps * 128;
        #pragma unroll
        for (int c = 0; c < 4; c++) {
            cp_async16(s0 + c * 16, pA + kb + c * 16, szA);
            cp_async16(s0 + HTILE_E * 2 + c * 16, pB + kb + c * 16, 16);
        }
        cp_commit();
    }

    for (int t = 0; t < nt; t++) {
        cp_wait<1>();
        __syncthreads();

        int tl = t + HSTAGES - 1;
        if (tl < nt) {
            uint32_t s0 = smemb + (uint32_t)(tl % HSTAGES) * (HSTAGE_E * 2) + sbase;
            uint32_t kb = (uint32_t)tl * 128;
            #pragma unroll
            for (int c = 0; c < 4; c++) {
                cp_async16(s0 + c * 16, pA + kb + c * 16, szA);
                cp_async16(s0 + HTILE_E * 2 + c * 16, pB + kb + c * 16, 16);
            }
            cp_commit();
        } else {
            cp_commit();   // lockstep for cp_wait<1>
        }

        uint32_t st = smemb + (uint32_t)(t % HSTAGES) * (HSTAGE_E * 2);
        #pragma unroll
        for (int ks = 0; ks < 64; ks += 16) {
            uint32_t Bf[8], Afr[16];
            {
                uint32_t r0 = (uint32_t)((wn * 32 + b_row) * ROWE + ks + b_k) * 2;
                uint32_t r1 = (uint32_t)((wn * 32 + 16 + b_row) * ROWE + ks + b_k) * 2;
                ldsm4(Bf + 0, st + (uint32_t)(HTILE_E) * 2 + r0);
                ldsm4(Bf + 4, st + (uint32_t)(HTILE_E) * 2 + r1);
            }
            #pragma unroll
            for (int mi = 0; mi < 4; mi++) {
                uint32_t ra = (uint32_t)((wm * 64 + mi * 16 + a_row) * ROWE + ks + a_k) * 2;
                ldsm4(&Afr[mi * 4], st + ra);
            }
            #pragma unroll
            for (int mi = 0; mi < 4; mi++)
                #pragma unroll
                for (int nj = 0; nj < 4; nj++)
                    mma16816_h(acc[mi][nj], &Afr[mi * 4], &Bf[nj * 2]);
        }
    }

    #pragma unroll
    for (int mi = 0; mi < 4; mi++) {
        int rb = bm + wm * 64 + mi * 16 + (lane >> 2);
        #pragma unroll
        for (int hf = 0; hf < 2; hf++) {
            int r = rb + hf * 8;
            if (r >= M) continue;
            int win = 0, n = 0;
            if (EPI == 0 || EPI == 1) { win = r / 196; n = r % 196; }
            bool pvalid = true; size_t pixbase = 0;
            if (EPI == 1) {
                int b = win / 25, wi = (win % 25) / 5, wj = win % 5;
                int ph = wi * 14 + n / 14, pw = wj * 14 + n % 14;
                pvalid = (ph < 64 && pw < 64);
                pixbase = ((size_t)((b * 64 + ph) * 64 + pw)) * 768;
            }
            #pragma unroll
            for (int nj = 0; nj < 4; nj++) {
                float v0 = acc[mi][nj][hf * 2 + 0];
                float v1 = acc[mi][nj][hf * 2 + 1];
                int col = bn + wn * 32 + nj * 8 + (lane & 3) * 2;
                v0 += bias[col]; v1 += bias[col + 1];
                if (EPI == 0) {
                    int which = col / 768;
                    int rem = col - which * 768;
                    int hh = rem >> 6, d = rem & 63;
                    size_t base = ((((size_t)which * NBH) + (size_t)win * 12 + hh)
                                   * NTOK + n) * 64 + d;
                    *(__half2*)&Ch[base] = __floats2half2_rn(v0, v1);
                } else if (EPI == 1) {
                    if (pvalid) {
                        size_t idx = pixbase + col;
                        float2 e = *(const float2*)(extra + idx);
                        *(float2*)&Cf[idx] = make_float2(v0 + e.x, v1 + e.y);
                    }
                } else if (EPI == 2) {
                    size_t idx = (size_t)r * N + col;
                    *(__half2*)(Ch + idx) =
                        __floats2half2_rn(gelu_exact(v0), gelu_exact(v1));
                } else {
                    size_t idx = (size_t)r * N + col;
                    float2 e = *(const float2*)(extra + idx);
                    *(float2*)&Cf[idx] = make_float2(v0 + e.x, v1 + e.y);
                }
            }
        }
    }
}

// ---------------------------------------------------------------------------
// Launch
// ---------------------------------------------------------------------------
static float* sym_f(const void* s) { void* p = nullptr; cudaGetSymbolAddress(&p, s); return (float*)p; }
static __half* sym_h(const void* s) { void* p = nullptr; cudaGetSymbolAddress(&p, s); return (__half*)p; }

extern "C" void kernel_launch(void* const* d_in, const int* in_sizes, int n_in,
                              void* d_out, int out_size) {
    const float* x     = (const float*)d_in[0];
    const float* n1g   = (const float*)d_in[1];
    const float* n1b   = (const float*)d_in[2];
    const float* qkvw  = (const float*)d_in[3];
    const float* qkvb  = (const float*)d_in[4];
    const float* projw = (const float*)d_in[5];
    const float* projb = (const float*)d_in[6];
    const float* rph   = (const float*)d_in[7];
    const float* rpw   = (const float*)d_in[8];
    const float* n2g   = (const float*)d_in[9];
    const float* n2b   = (const float*)d_in[10];
    const float* w1    = (const float*)d_in[11];
    const float* b1    = (const float*)d_in[12];
    const float* w2    = (const float*)d_in[13];
    const float* b2    = (const float*)d_in[14];
    float* out = (float*)d_out;

    float* p_x1   = sym_f(g_x1);
    __half *qkvh = sym_h(g_qkv_h);
    __half *winh = sym_h(g_win_h);
    __half *atth = sym_h(g_att_h);
    __half *ln2h = sym_h(g_ln2_h);
    __half *mlph = sym_h(g_mlp_h);
    __half *qwh  = sym_h(g_qkvwt_h);
    __half *pwh  = sym_h(g_projwt_h);
    __half *w1h  = sym_h(g_w1t_h);
    __half *w2h  = sym_h(g_w2t_h);

    cudaFuncSetAttribute(attn_tc_kernel, cudaFuncAttributeMaxDynamicSharedMemorySize,
                         ATC_SMEM);
    cudaFuncSetAttribute(hgemm<0>, cudaFuncAttributeMaxDynamicSharedMemorySize, HGEMM_SMEM);
    cudaFuncSetAttribute(hgemm<1>, cudaFuncAttributeMaxDynamicSharedMemorySize, HGEMM_SMEM);
    cudaFuncSetAttribute(hgemm<2>, cudaFuncAttributeMaxDynamicSharedMemorySize, HGEMM_SMEM);
    cudaFuncSetAttribute(hgemm<3>, cudaFuncAttributeMaxDynamicSharedMemorySize, HGEMM_SMEM);

    // 0) merged weight transposes -> fp16 [N,K]  (one launch for all four)
    tsplit_all_kernel<<<6912, 256>>>(qkvw, projw, w1, w2, qwh, pwh, w1h, w2h);

    // 1) LN1 + window partition -> fp16
    ln_h_kernel<<<TOKS, 256>>>(x, n1g, n1b, winh, 1);

    // 2) QKV GEMM (fp16) -> fp16 q/k/v scatter
    hgemm<0><<<dim3(2304 / 128, (TOKS + 127) / 128), 256, HGEMM_SMEM>>>(
        winh, qwh, qkvb, nullptr, qkvh, nullptr, TOKS, 2304, 768);

    // 3) tensor-core attention with fused rel-pos bias -> fp16
    attn_tc_kernel<<<NBH, ATHREADS, ATC_SMEM>>>(qkvh, rph, rpw, atth);

    // 4) proj GEMM (fp16) + unpartition + residual -> fp32 x1
    hgemm<1><<<dim3(768 / 128, (TOKS + 127) / 128), 256, HGEMM_SMEM>>>(
        atth, pwh, projb, p_x1, nullptr, x, TOKS, 768, 768);

    // 5) LN2 -> fp16
    ln_h_kernel<<<PIX, 256>>>(p_x1, n2g, n2b, ln2h, 0);

    // 6) MLP fc1 (fp16) + GELU -> fp16
    hgemm<2><<<dim3(3072 / 128, PIX / 128), 256, HGEMM_SMEM>>>(
        ln2h, w1h, b1, nullptr, mlph, nullptr, PIX, 3072, 768);

    // 7) MLP fc2 (fp16) + residual -> final fp32 output
    hgemm<3><<<dim3(768 / 128, PIX / 128), 256, HGEMM_SMEM>>>(
        mlph, w2h, b2, out, nullptr, p_x1, PIX, 768, 3072);

    (void)in_sizes; (void)n_in; (void)out_size;
}

// round 17
// speedup vs baseline: 1.0542x; 1.0174x over previous
#include <cuda_runtime.h>
#include <cuda_fp16.h>
#include <math.h>
#include <stdint.h>

// ---------------------------------------------------------------------------
// Problem constants
// ---------------------------------------------------------------------------
#define TOKS 19600
#define PIX  16384
#define NBH  1200
#define NTOK 196

// ---------------------------------------------------------------------------
// Scratch (static __device__ arrays; no allocation anywhere)
// ---------------------------------------------------------------------------
__device__ float g_x1  [16384u * 768u];             // residual-1 (fp32)

__device__ __align__(256) __half g_qkv_h[3u * 1200u * 196u * 64u]; // [w][bh][n][d]
__device__ __align__(256) __half g_win_h[19600u * 768u];   // LN1+partition
__device__ __align__(256) __half g_att_h[19600u * 768u];
__device__ __align__(256) __half g_ln2_h[16384u * 768u];
__device__ __align__(256) __half g_mlp_h[16384u * 3072u];
// transposed (N-major, K contiguous) fp16 weights
__device__ __align__(256) __half g_qkvwt_h[2304u * 768u];
__device__ __align__(256) __half g_projwt_h[768u * 768u];
__device__ __align__(256) __half g_w1t_h[3072u * 768u];
__device__ __align__(256) __half g_w2t_h[768u * 3072u];

// ---------------------------------------------------------------------------
// PTX helpers — sm_80-era features only (harness PTX pass targets plain
// sm_103 which rejects tcgen05/TMEM; mma.sync/ldmatrix/cp.async are fine).
// ---------------------------------------------------------------------------
__device__ __forceinline__ uint32_t smem_u32(const void* p) {
    uint32_t a;
    asm("{ .reg .u64 t; cvta.to.shared.u64 t, %1; cvt.u32.u64 %0, t; }"
        : "=r"(a) : "l"(p));
    return a;
}
__device__ __forceinline__ void cp_async16(uint32_t s, const void* g, uint32_t sz) {
    asm volatile("cp.async.cg.shared.global [%0], [%1], 16, %2;"
                 :: "r"(s), "l"(g), "r"(sz) : "memory");
}
__device__ __forceinline__ void cp_commit() {
    asm volatile("cp.async.commit_group;" ::: "memory");
}
template <int N> __device__ __forceinline__ void cp_wait() {
    asm volatile("cp.async.wait_group %0;" :: "n"(N) : "memory");
}
__device__ __forceinline__ void ldsm4(uint32_t* r, uint32_t addr) {
    asm volatile("ldmatrix.sync.aligned.m8n8.x4.shared.b16 {%0,%1,%2,%3}, [%4];"
                 : "=r"(r[0]), "=r"(r[1]), "=r"(r[2]), "=r"(r[3]) : "r"(addr));
}
__device__ __forceinline__ void mma16816_h(float* c, const uint32_t* a,
                                           const uint32_t* b) {
    asm volatile(
        "mma.sync.aligned.m16n8k16.row.col.f32.f16.f16.f32 "
        "{%0,%1,%2,%3}, {%4,%5,%6,%7}, {%8,%9}, {%0,%1,%2,%3};"
        : "+f"(c[0]), "+f"(c[1]), "+f"(c[2]), "+f"(c[3])
        : "r"(a[0]), "r"(a[1]), "r"(a[2]), "r"(a[3]), "r"(b[0]), "r"(b[1]));
}
__device__ __forceinline__ float gelu_exact(float x) {
    return 0.5f * x * (1.0f + erff(x * 0.70710678118654752440f));
}
// FMA-pipe exp (avoids the 0.5/cyc/SM MUFU bottleneck). Valid for x <= 0,
// rel err ~4e-5.
__device__ __forceinline__ float fexp(float x) {
    x = fmaxf(x, -80.0f);
    float y = x * 1.44269504f;
    float t = __fadd_rn(y, 12582912.0f);
    int ni = __float_as_int(t) - 0x4B400000;
    float f = __fsub_rn(y, __fsub_rn(t, 12582912.0f));
    float p = 0.009618130f;
    p = fmaf(p, f, 0.055504110f);
    p = fmaf(p, f, 0.240226507f);
    p = fmaf(p, f, 0.693147181f);
    p = fmaf(p, f, 1.0f);
    return __int_as_float(__float_as_int(p) + (ni << 23));
}

// ---------------------------------------------------------------------------
// LN (+ optional window-partition gather) -> fp16
// ---------------------------------------------------------------------------
__global__ void ln_h_kernel(const float* __restrict__ in,
                            const float* __restrict__ gamma,
                            const float* __restrict__ beta,
                            __half* __restrict__ oh, int partition) {
    __shared__ float red_s[8], red_q[8];
    int r = blockIdx.x, t = threadIdx.x;
    size_t dst = (size_t)r * 768;
    const float* src;
    if (partition) {
        int wid = r / 196, n = r % 196;
        int b = wid / 25, wi = (wid % 25) / 5, wj = wid % 5;
        int hh = wi * 14 + n / 14, ww = wj * 14 + n % 14;
        if (hh >= 64 || ww >= 64) {
            __half z = __float2half(0.0f);
            for (int c = t; c < 768; c += 256) oh[dst + c] = z;
            return;
        }
        src = in + ((size_t)((b * 64 + hh) * 64 + ww)) * 768;
    } else {
        src = in + (size_t)r * 768;
    }
    float v0 = src[t], v1 = src[t + 256], v2 = src[t + 512];
    float s = v0 + v1 + v2, q = v0 * v0 + v1 * v1 + v2 * v2;
    #pragma unroll
    for (int off = 16; off > 0; off >>= 1) {
        s += __shfl_xor_sync(0xffffffffu, s, off);
        q += __shfl_xor_sync(0xffffffffu, q, off);
    }
    int warp = t >> 5, lane = t & 31;
    if (lane == 0) { red_s[warp] = s; red_q[warp] = q; }
    __syncthreads();
    float st = 0.f, qt = 0.f;
    #pragma unroll
    for (int i = 0; i < 8; i++) { st += red_s[i]; qt += red_q[i]; }
    float mean = st * (1.0f / 768.0f);
    float var  = qt * (1.0f / 768.0f) - mean * mean;
    float rstd = rsqrtf(var + 1e-5f);
    #pragma unroll
    for (int k = 0; k < 3; k++) {
        int c = t + k * 256;
        float vv = (k == 0 ? v0 : (k == 1 ? v1 : v2));
        oh[dst + c] = __float2half((vv - mean) * rstd * gamma[c] + beta[c]);
    }
}

// ---------------------------------------------------------------------------
// Merged weight transpose: all 4 weights in ONE launch.
// ---------------------------------------------------------------------------
__global__ void tsplit_all_kernel(const float* __restrict__ Wq,
                                  const float* __restrict__ Wp,
                                  const float* __restrict__ W1,
                                  const float* __restrict__ W2,
                                  __half* __restrict__ Tq,
                                  __half* __restrict__ Tp,
                                  __half* __restrict__ T1,
                                  __half* __restrict__ T2) {
    __shared__ float tile[32][33];
    int b = blockIdx.x;
    const float* W; __half* T; int Kd, Nd, bx;
    if (b < 1728)        { W = Wq; T = Tq; Kd = 768;  Nd = 2304; bx = b; }
    else if (b < 2304)   { W = Wp; T = Tp; Kd = 768;  Nd = 768;  bx = b - 1728; }
    else if (b < 4608)   { W = W1; T = T1; Kd = 768;  Nd = 3072; bx = b - 2304; }
    else                 { W = W2; T = T2; Kd = 3072; Nd = 768;  bx = b - 4608; }
    int nbx = Nd / 32;
    int n0 = (bx % nbx) * 32, k0 = (bx / nbx) * 32;
    int tx = threadIdx.x & 31, ty = threadIdx.x >> 5;
    #pragma unroll
    for (int i = 0; i < 4; i++)
        tile[ty + i * 8][tx] = W[(size_t)(k0 + ty + i * 8) * Nd + n0 + tx];
    __syncthreads();
    #pragma unroll
    for (int i = 0; i < 4; i++) {
        int n = n0 + ty + i * 8, k = k0 + tx;
        T[(size_t)n * Kd + k] = __float2half(tile[tx][ty + i * 8]);
    }
}

// ---------------------------------------------------------------------------
// Tensor-core attention, 13 warps, one strip per warp, fused rel-pos bias.
// R17: Q/K/RT staging via cp.async (zero-fill handles padding) overlapped
// with the scalar Vt transpose; exp-sum split into 2 chains.
// ---------------------------------------------------------------------------
#define ATHREADS 416
#define OFF_Q 0
#define OFF_K 29952
#define OFF_V 62208
#define OFF_S 91904
#define OFF_RT (OFF_S + 13 * 7424)          // 188416: rel tables 2 x 27x64 f32
#define OFF_RH (OFF_RT + 13824)             // 202240: relh 196x14 f32
#define OFF_RW (OFF_RH + 10976)             // 213216: relw 196x14 f32
#define ATC_SMEM (OFF_RW + 10976)           // 224192 B

__global__ __launch_bounds__(ATHREADS)
void attn_tc_kernel(const __half* __restrict__ qkv,
                    const float* __restrict__ rph,
                    const float* __restrict__ rpw,
                    __half* __restrict__ outh) {
    extern __shared__ char asmem[];
    uint32_t smemb = smem_u32(asmem);
    __half* Qs = (__half*)(asmem + OFF_Q);   // stride 72
    __half* Vt = (__half*)(asmem + OFF_V);   // stride 232, [ch][tok]
    float* RTh = (float*)(asmem + OFF_RT);          // 27x64
    float* RTw = (float*)(asmem + OFF_RT + 6912);   // 27x64
    float* RelHs = (float*)(asmem + OFF_RH);        // [196][14]
    float* RelWs = (float*)(asmem + OFF_RW);        // [196][14]

    int bh = blockIdx.x;
    int tid = threadIdx.x, warp = tid >> 5, lane = tid & 31;
    const __half* qp = qkv + ((size_t)0 * NBH + bh) * NTOK * 64;
    const __half* kp = qkv + ((size_t)1 * NBH + bh) * NTOK * 64;
    const __half* vp = qkv + ((size_t)2 * NBH + bh) * NTOK * 64;

    // ---- async staging of Q (208 rows), K (224 rows), rel tables ----
    // cp.async src-size 0 zero-fills the 16B chunk (handles padded rows).
    for (int idx = tid; idx < 208 * 8; idx += ATHREADS) {
        int row = idx >> 3, c8 = (idx & 7) * 8;
        cp_async16(smemb + OFF_Q + (uint32_t)(row * 72 + c8) * 2,
                   qp + row * 64 + c8, (row < 196) ? 16u : 0u);
    }
    for (int idx = tid; idx < 224 * 8; idx += ATHREADS) {
        int row = idx >> 3, c8 = (idx & 7) * 8;
        cp_async16(smemb + OFF_K + (uint32_t)(row * 72 + c8) * 2,
                   kp + row * 64 + c8, (row < 196) ? 16u : 0u);
    }
    for (int idx = tid; idx < 864; idx += ATHREADS) {
        const char* src = (idx < 432) ? (const char*)rph + idx * 16
                                      : (const char*)rpw + (idx - 432) * 16;
        cp_async16(smemb + OFF_RT + (uint32_t)idx * 16, src, 16);
    }
    cp_commit();

    // ---- scalar Vt transpose overlaps the async copies above ----
    for (int idx = tid; idx < 224 * 64; idx += ATHREADS) {
        int tok = idx >> 6, ch = idx & 63;
        Vt[ch * 232 + tok] = (tok < 196) ? vp[tok * 64 + ch] : __float2half(0.f);
    }
    cp_wait<0>();
    __syncthreads();

    // ---- fused rel-pos bias, k-major mapping, half2/float2 vectorized ----
    for (int p = tid; p < 14 * 196; p += ATHREADS) {
        int ki = p / 196, row = p % 196;
        const __half2* q2 = (const __half2*)(Qs + row * 72);
        const float2* rp2 = (const float2*)(RTh + (row / 14 - ki + 13) * 64);
        float s = 0.f;
        #pragma unroll 8
        for (int c2 = 0; c2 < 32; c2++) {
            float2 qf = __half22float2(q2[c2]);
            float2 rv = rp2[c2];
            s = fmaf(qf.x, rv.x, s);
            s = fmaf(qf.y, rv.y, s);
        }
        RelHs[row * 14 + ki] = s;
    }
    for (int p = tid; p < 14 * 196; p += ATHREADS) {
        int kj = p / 196, rem = p % 196;
        int qj = rem / 14, qi = rem % 14;
        int row = qi * 14 + qj;
        const __half2* q2 = (const __half2*)(Qs + row * 72);
        const float2* rp2 = (const float2*)(RTw + (qj - kj + 13) * 64);
        float s = 0.f;
        #pragma unroll 8
        for (int c2 = 0; c2 < 32; c2++) {
            float2 qf = __half22float2(q2[c2]);
            float2 rv = rp2[c2];
            s = fmaf(qf.x, rv.x, s);
            s = fmaf(qf.y, rv.y, s);
        }
        RelWs[row * 14 + kj] = s;
    }
    __syncthreads();

    int win = bh / 12, h = bh % 12;
    size_t obase = (size_t)win * NTOK * 768 + h * 64;

    int a_row = (lane & 7) + ((lane >> 3) & 1) * 8;
    int a_k   = (lane >> 4) * 8;
    int b_row = (lane & 7) + (lane >> 4) * 8;
    int b_k   = ((lane >> 3) & 1) * 8;

    __half* Sp = (__half*)(asmem + OFF_S + warp * 7424);       // [16][232]
    uint32_t sbase_w = smemb + OFF_S + (uint32_t)warp * 7424;

    {
        int strip = warp;               // 0..12, one strip per warp
        int row0 = strip * 16;

        // ---------- S = Q @ K^T ----------
        uint32_t Af[16];
        {
            uint32_t qb = smemb + OFF_Q + (uint32_t)((row0 + a_row) * 72) * 2;
            #pragma unroll
            for (int kt = 0; kt < 4; kt++)
                ldsm4(&Af[kt * 4], qb + (uint32_t)(kt * 16 + a_k) * 2);
        }
        #pragma unroll 2
        for (int n2 = 0; n2 < 14; n2++) {
            uint32_t Bf[16];
            uint32_t kb = smemb + OFF_K + (uint32_t)((n2 * 16 + b_row) * 72) * 2;
            #pragma unroll
            for (int kt = 0; kt < 4; kt++)
                ldsm4(&Bf[kt * 4], kb + (uint32_t)(kt * 16 + b_k) * 2);
            float ac0[4] = {0.f, 0.f, 0.f, 0.f};
            float ac1[4] = {0.f, 0.f, 0.f, 0.f};
            #pragma unroll
            for (int kt = 0; kt < 4; kt++) {
                mma16816_h(ac0, &Af[kt * 4], &Bf[kt * 4]);
                mma16816_h(ac1, &Af[kt * 4], &Bf[kt * 4 + 2]);
            }
            int r = lane >> 2, cc = (lane & 3) * 2;
            int col = n2 * 16 + cc;
            *(__half2*)(Sp + r * 232 + col)           = __floats2half2_rn(ac0[0], ac0[1]);
            *(__half2*)(Sp + (r + 8) * 232 + col)     = __floats2half2_rn(ac0[2], ac0[3]);
            *(__half2*)(Sp + r * 232 + col + 8)       = __floats2half2_rn(ac1[0], ac1[1]);
            *(__half2*)(Sp + (r + 8) * 232 + col + 8) = __floats2half2_rn(ac1[2], ac1[3]);
        }
        __syncwarp();

        // ---------- softmax: 2 lanes/row, half2-vectorized passes ----------
        float inv;
        {
            int srow = lane >> 1, half_ = lane & 1;
            int qrow = row0 + srow;
            int rr = qrow < 196 ? qrow : 195;
            const float* RH = RelHs + rr * 14;
            const float* RW = RelWs + rr * 14;
            float rwv[14];
            #pragma unroll
            for (int j = 0; j < 14; j++) rwv[j] = RW[j];
            __half2* S2 = (__half2*)(Sp + srow * 232 + half_ * 112);
            int ki0 = half_ * 8;
            int nki = half_ ? 6 : 8;        // valid cols: 112 or 84
            float m = -1e30f;
            int c2 = 0;
            for (int ib = 0; ib < nki; ib++) {
                float rh = RH[ki0 + ib];
                #pragma unroll
                for (int j2 = 0; j2 < 7; j2++) {
                    float2 f = __half22float2(S2[c2]);
                    float v0 = f.x * 0.125f + rh + rwv[j2 * 2];
                    float v1 = f.y * 0.125f + rh + rwv[j2 * 2 + 1];
                    S2[c2] = __floats2half2_rn(v0, v1);
                    m = fmaxf(m, fmaxf(v0, v1));
                    c2++;
                }
            }
            m = fmaxf(m, __shfl_xor_sync(0xffffffffu, m, 1));
            float sum0 = 0.f, sum1 = 0.f;
            c2 = 0;
            for (int ib = 0; ib < nki; ib++) {
                #pragma unroll
                for (int j2 = 0; j2 < 7; j2++) {
                    float2 f = __half22float2(S2[c2]);
                    float e0 = fexp(f.x - m);
                    float e1 = fexp(f.y - m);
                    sum0 += e0;
                    sum1 += e1;
                    S2[c2] = __floats2half2_rn(e0, e1);
                    c2++;
                }
            }
            float sum = sum0 + sum1;
            sum += __shfl_xor_sync(0xffffffffu, sum, 1);
            inv = 1.0f / sum;
        }
        __syncwarp();

        // ---------- O = P @ V ----------
        float oacc[8][4];
        #pragma unroll
        for (int i = 0; i < 8; i++)
            #pragma unroll
            for (int j = 0; j < 4; j++) oacc[i][j] = 0.f;
        #pragma unroll 2
        for (int kt = 0; kt < 14; kt++) {
            uint32_t Pf[4];
            ldsm4(Pf, sbase_w + (uint32_t)(a_row * 232 + kt * 16 + a_k) * 2);
            #pragma unroll
            for (int nd = 0; nd < 4; nd++) {
                uint32_t Vf[4];
                ldsm4(Vf, smemb + OFF_V +
                      (uint32_t)((nd * 16 + b_row) * 232 + kt * 16 + b_k) * 2);
                mma16816_h(oacc[nd * 2 + 0], Pf, &Vf[0]);
                mma16816_h(oacc[nd * 2 + 1], Pf, &Vf[2]);
            }
        }

        {
            int r0 = lane >> 2;
            float inv0 = __shfl_sync(0xffffffffu, inv, r0 * 2);
            float inv1 = __shfl_sync(0xffffffffu, inv, (r0 + 8) * 2);
            int g0 = row0 + r0, g1 = g0 + 8;
            int colb = (lane & 3) * 2;
            #pragma unroll
            for (int nt = 0; nt < 8; nt++) {
                int col = nt * 8 + colb;
                if (g0 < 196)
                    *(__half2*)(outh + obase + (size_t)g0 * 768 + col) =
                        __floats2half2_rn(oacc[nt][0] * inv0, oacc[nt][1] * inv0);
                if (g1 < 196)
                    *(__half2*)(outh + obase + (size_t)g1 * 768 + col) =
                        __floats2half2_rn(oacc[nt][2] * inv1, oacc[nt][3] * inv1);
            }
        }
    }
}

// ---------------------------------------------------------------------------
// Single-term fp16 GEMM (EXACT R13 config — proven): 8 warps, warp tile
// 64x32, 2 CTAs/SM, BK=64, 3 stages, one barrier per K-iter.
// EPI 0: qkv  — bias + scatter to g_qkv_h (fp16)
// EPI 1: proj — unpartition + residual -> fp32
// EPI 2: mlp1 — gelu -> fp16
// EPI 3: mlp2 — residual -> fp32 out
// ---------------------------------------------------------------------------
#define ROWE 72                         // 64 + 8 pad halves per row
#define HTILE_E (128 * ROWE)            // 9216 halves per operand tile
#define HSTAGE_E (2 * HTILE_E)          // A + B
#define HSTAGES 3
#define HGEMM_SMEM (HSTAGES * HSTAGE_E * 2)   // 110592 B

template <int EPI>
__global__ __launch_bounds__(256, 2)
void hgemm(const __half* __restrict__ A, const __half* __restrict__ B,
           const float* __restrict__ bias, float* __restrict__ Cf,
           __half* __restrict__ Ch, const float* __restrict__ extra,
           int M, int N, int K) {
    extern __shared__ __align__(16) __half smh[];
    uint32_t smemb = smem_u32(smh);

    int tid = threadIdx.x;
    int bm = blockIdx.y * 128, bn = blockIdx.x * 128;
    int lane = tid & 31, warp = tid >> 5;
    int wm = warp & 1, wn = warp >> 1;

    int lrow = tid >> 1;
    int c4   = (tid & 1) * 4;
    uint32_t sbase = (uint32_t)(lrow * ROWE + c4 * 8) * 2;
    int rowA = bm + lrow; bool va = rowA < M;
    int rowB = bn + lrow;
    const char* pA = (const char*)(A + (size_t)(va ? rowA : 0) * K) + c4 * 16;
    const char* pB = (const char*)(B + (size_t)rowB * K) + c4 * 16;
    uint32_t szA = va ? 16u : 0u;

    int a_row = (lane & 7) + ((lane >> 3) & 1) * 8;
    int a_k   = (lane >> 4) * 8;
    int b_row = (lane & 7) + (lane >> 4) * 8;
    int b_k   = ((lane >> 3) & 1) * 8;

    float acc[4][4][4];
    #pragma unroll
    for (int i = 0; i < 4; i++)
        #pragma unroll
        for (int j = 0; j < 4; j++)
            #pragma unroll
            for (int k = 0; k < 4; k++) acc[i][j][k] = 0.f;

    const int nt = K / 64;

    #pragma unroll
    for (int ps = 0; ps < HSTAGES - 1; ps++) {
        uint32_t s0 = smemb + (uint32_t)ps * (HSTAGE_E * 2) + sbase;
        uint32_t kb = (uint32_t)ps * 128;
        #pragma unroll
        for (int c = 0; c < 4; c++) {
            cp_async16(s0 + c * 16, pA + kb + c * 16, szA);
            cp_async16(s0 + HTILE_E * 2 + c * 16, pB + kb + c * 16, 16);
        }
        cp_commit();
    }

    for (int t = 0; t < nt; t++) {
        cp_wait<1>();
        __syncthreads();

        int tl = t + HSTAGES - 1;
        if (tl < nt) {
            uint32_t s0 = smemb + (uint32_t)(tl % HSTAGES) * (HSTAGE_E * 2) + sbase;
            uint32_t kb = (uint32_t)tl * 128;
            #pragma unroll
            for (int c = 0; c < 4; c++) {
                cp_async16(s0 + c * 16, pA + kb + c * 16, szA);
                cp_async16(s0 + HTILE_E * 2 + c * 16, pB + kb + c * 16, 16);
            }
            cp_commit();
        } else {
            cp_commit();   // lockstep for cp_wait<1>
        }

        uint32_t st = smemb + (uint32_t)(t % HSTAGES) * (HSTAGE_E * 2);
        #pragma unroll
        for (int ks = 0; ks < 64; ks += 16) {
            uint32_t Bf[8], Afr[16];
            {
                uint32_t r0 = (uint32_t)((wn * 32 + b_row) * ROWE + ks + b_k) * 2;
                uint32_t r1 = (uint32_t)((wn * 32 + 16 + b_row) * ROWE + ks + b_k) * 2;
                ldsm4(Bf + 0, st + (uint32_t)(HTILE_E) * 2 + r0);
                ldsm4(Bf + 4, st + (uint32_t)(HTILE_E) * 2 + r1);
            }
            #pragma unroll
            for (int mi = 0; mi < 4; mi++) {
                uint32_t ra = (uint32_t)((wm * 64 + mi * 16 + a_row) * ROWE + ks + a_k) * 2;
                ldsm4(&Afr[mi * 4], st + ra);
            }
            #pragma unroll
            for (int mi = 0; mi < 4; mi++)
                #pragma unroll
                for (int nj = 0; nj < 4; nj++)
                    mma16816_h(acc[mi][nj], &Afr[mi * 4], &Bf[nj * 2]);
        }
    }

    #pragma unroll
    for (int mi = 0; mi < 4; mi++) {
        int rb = bm + wm * 64 + mi * 16 + (lane >> 2);
        #pragma unroll
        for (int hf = 0; hf < 2; hf++) {
            int r = rb + hf * 8;
            if (r >= M) continue;
            int win = 0, n = 0;
            if (EPI == 0 || EPI == 1) { win = r / 196; n = r % 196; }
            bool pvalid = true; size_t pixbase = 0;
            if (EPI == 1) {
                int b = win / 25, wi = (win % 25) / 5, wj = win % 5;
                int ph = wi * 14 + n / 14, pw = wj * 14 + n % 14;
                pvalid = (ph < 64 && pw < 64);
                pixbase = ((size_t)((b * 64 + ph) * 64 + pw)) * 768;
            }
            #pragma unroll
            for (int nj = 0; nj < 4; nj++) {
                float v0 = acc[mi][nj][hf * 2 + 0];
                float v1 = acc[mi][nj][hf * 2 + 1];
                int col = bn + wn * 32 + nj * 8 + (lane & 3) * 2;
                v0 += bias[col]; v1 += bias[col + 1];
                if (EPI == 0) {
                    int which = col / 768;
                    int rem = col - which * 768;
                    int hh = rem >> 6, d = rem & 63;
                    size_t base = ((((size_t)which * NBH) + (size_t)win * 12 + hh)
                                   * NTOK + n) * 64 + d;
                    *(__half2*)&Ch[base] = __floats2half2_rn(v0, v1);
                } else if (EPI == 1) {
                    if (pvalid) {
                        size_t idx = pixbase + col;
                        float2 e = *(const float2*)(extra + idx);
                        *(float2*)&Cf[idx] = make_float2(v0 + e.x, v1 + e.y);
                    }
                } else if (EPI == 2) {
                    size_t idx = (size_t)r * N + col;
                    *(__half2*)(Ch + idx) =
                        __floats2half2_rn(gelu_exact(v0), gelu_exact(v1));
                } else {
                    size_t idx = (size_t)r * N + col;
                    float2 e = *(const float2*)(extra + idx);
                    *(float2*)&Cf[idx] = make_float2(v0 + e.x, v1 + e.y);
                }
            }
        }
    }
}

// ---------------------------------------------------------------------------
// Launch
// ---------------------------------------------------------------------------
static float* sym_f(const void* s) { void* p = nullptr; cudaGetSymbolAddress(&p, s); return (float*)p; }
static __half* sym_h(const void* s) { void* p = nullptr; cudaGetSymbolAddress(&p, s); return (__half*)p; }

extern "C" void kernel_launch(void* const* d_in, const int* in_sizes, int n_in,
                              void* d_out, int out_size) {
    const float* x     = (const float*)d_in[0];
    const float* n1g   = (const float*)d_in[1];
    const float* n1b   = (const float*)d_in[2];
    const float* qkvw  = (const float*)d_in[3];
    const float* qkvb  = (const float*)d_in[4];
    const float* projw = (const float*)d_in[5];
    const float* projb = (const float*)d_in[6];
    const float* rph   = (const float*)d_in[7];
    const float* rpw   = (const float*)d_in[8];
    const float* n2g   = (const float*)d_in[9];
    const float* n2b   = (const float*)d_in[10];
    const float* w1    = (const float*)d_in[11];
    const float* b1    = (const float*)d_in[12];
    const float* w2    = (const float*)d_in[13];
    const float* b2    = (const float*)d_in[14];
    float* out = (float*)d_out;

    float* p_x1   = sym_f(g_x1);
    __half *qkvh = sym_h(g_qkv_h);
    __half *winh = sym_h(g_win_h);
    __half *atth = sym_h(g_att_h);
    __half *ln2h = sym_h(g_ln2_h);
    __half *mlph = sym_h(g_mlp_h);
    __half *qwh  = sym_h(g_qkvwt_h);
    __half *pwh  = sym_h(g_projwt_h);
    __half *w1h  = sym_h(g_w1t_h);
    __half *w2h  = sym_h(g_w2t_h);

    cudaFuncSetAttribute(attn_tc_kernel, cudaFuncAttributeMaxDynamicSharedMemorySize,
                         ATC_SMEM);
    cudaFuncSetAttribute(hgemm<0>, cudaFuncAttributeMaxDynamicSharedMemorySize, HGEMM_SMEM);
    cudaFuncSetAttribute(hgemm<1>, cudaFuncAttributeMaxDynamicSharedMemorySize, HGEMM_SMEM);
    cudaFuncSetAttribute(hgemm<2>, cudaFuncAttributeMaxDynamicSharedMemorySize, HGEMM_SMEM);
    cudaFuncSetAttribute(hgemm<3>, cudaFuncAttributeMaxDynamicSharedMemorySize, HGEMM_SMEM);

    // 0) merged weight transposes -> fp16 [N,K]  (one launch for all four)
    tsplit_all_kernel<<<6912, 256>>>(qkvw, projw, w1, w2, qwh, pwh, w1h, w2h);

    // 1) LN1 + window partition -> fp16
    ln_h_kernel<<<TOKS, 256>>>(x, n1g, n1b, winh, 1);

    // 2) QKV GEMM (fp16) -> fp16 q/k/v scatter
    hgemm<0><<<dim3(2304 / 128, (TOKS + 127) / 128), 256, HGEMM_SMEM>>>(
        winh, qwh, qkvb, nullptr, qkvh, nullptr, TOKS, 2304, 768);

    // 3) tensor-core attention with fused rel-pos bias -> fp16
    attn_tc_kernel<<<NBH, ATHREADS, ATC_SMEM>>>(qkvh, rph, rpw, atth);

    // 4) proj GEMM (fp16) + unpartition + residual -> fp32 x1
    hgemm<1><<<dim3(768 / 128, (TOKS + 127) / 128), 256, HGEMM_SMEM>>>(
        atth, pwh, projb, p_x1, nullptr, x, TOKS, 768, 768);

    // 5) LN2 -> fp16
    ln_h_kernel<<<PIX, 256>>>(p_x1, n2g, n2b, ln2h, 0);

    // 6) MLP fc1 (fp16) + GELU -> fp16
    hgemm<2><<<dim3(3072 / 128, PIX / 128), 256, HGEMM_SMEM>>>(
        ln2h, w1h, b1, nullptr, mlph, nullptr, PIX, 3072, 768);

    // 7) MLP fc2 (fp16) + residual -> final fp32 output
    hgemm<3><<<dim3(768 / 128, PIX / 128), 256, HGEMM_SMEM>>>(
        mlph, w2h, b2, out, nullptr, p_x1, PIX, 768, 3072);

    (void)in_sizes; (void)n_in; (void)out_size;
}